// round 13
// baseline (speedup 1.0000x reference)
#include <cuda_runtime.h>
#include <cuda_fp16.h>
#include <stdint.h>
#include <math.h>

// ---------------- problem constants ----------------
#define NCELLS 131072
#define MT   64
#define TPB  256
#define NBLK (NCELLS / MT)   // 2048

// ---------------- smem layout (float offsets) ----------------
// all half pitches are ≡ 16 (mod 128) BYTES -> ldmatrix 8-row groups conflict-free
#define HHP   136            // h_h half pitch   (272 B)
#define C1HP  136            // C1 half-buffer pitch (272 B, 128 cols + 8 pad)
#define OHP   72             // out_h half pitch (144 B)

#define OFF_HH   0                        // 64*136 h = 4352 floats
#define OFF_C1H  4352                     // 64*136 h = 4352 floats (half of C1, reused 2x)
#define OFF_OUTH 8704                     // 64*72 h  = 2304 floats
#define OFF_T    11008                    // 64
#define OFF_E    11072                    // 64
#define OFF_XC   11136                    // 256
#define OFF_B2D  11392                    // 64
#define OFF_BRZ  11456                    // 256
#define OFF_BNI  11712                    // 128
#define OFF_BNH  11840                    // 128
#define OFF_WT   11968                    // 384
#define SMEM_KB_FLOATS 12352
#define SMEM_KB_BYTES  (SMEM_KB_FLOATS * 4)   // 49408 B -> 3 blocks/SM (148 KB), L1D ~80 KB

// ---------------- device scratch (static, allocation-free) ----------------
__device__ uint2 g_B1h[8 * 32 * 32];     // stage1  K=128,N=256
__device__ uint2 g_B2h[16 * 8 * 32];     // stage2  K=256,N=64 (sign-folded)
__device__ uint2 g_B3h[8 * 48 * 32];     // GRU Whh K=128,N=384
__device__ uint2 g_B4h[4 * 48 * 32];     // GRU Wih K=64, N=384
__device__ float g_xc[256];
__device__ float g_b2d[64];
__device__ float g_brz[256];
__device__ float g_bni[128];
__device__ float g_bnh[128];
__device__ float g_wt[384];
__device__ float g_blk_t[NBLK];
__device__ float g_blk_e[NBLK];
__device__ float g_blk_wout[NBLK * 64];
__device__ float g_blk_h[NBLK * 128];
__device__ float g_fm[8 * 128];
__device__ float g_go[128];

// ---------------- helpers ----------------
__device__ __forceinline__ unsigned packh2(float lo, float hi) {
    __half2 h = __floats2half2_rn(lo, hi);
    return *(unsigned*)&h;
}
__device__ __forceinline__ void mma16(float* c,
    unsigned a0, unsigned a1, unsigned a2, unsigned a3,
    unsigned b0, unsigned b1)
{
    asm volatile(
        "mma.sync.aligned.m16n8k16.row.col.f32.f16.f16.f32 "
        "{%0,%1,%2,%3},{%4,%5,%6,%7},{%8,%9},{%0,%1,%2,%3};"
        : "+f"(c[0]), "+f"(c[1]), "+f"(c[2]), "+f"(c[3])
        : "r"(a0), "r"(a1), "r"(a2), "r"(a3), "r"(b0), "r"(b1));
}
__device__ __forceinline__ void ldsm4(unsigned& a0, unsigned& a1, unsigned& a2, unsigned& a3,
                                      unsigned addr)
{
    asm volatile("ldmatrix.sync.aligned.m8n8.x4.shared.b16 {%0,%1,%2,%3}, [%4];"
                 : "=r"(a0), "=r"(a1), "=r"(a2), "=r"(a3) : "r"(addr));
}
__device__ __forceinline__ float sigmoid_f(float x) {
    return 1.f / (1.f + __expf(-x));
}

// ---------------- kA1: pack B1h + B2h ----------------
__global__ __launch_bounds__(512) void kA1(
    const float* __restrict__ W1a, const float* __restrict__ W1g,
    const float* __restrict__ W2a, const float* __restrict__ W2g)
{
    int id = blockIdx.x * 512 + threadIdx.x;
    if (id < 8192) {                                  // B1h: B[k][u]=W1[u][64+k]
        int grp = id >> 10, rem = id & 1023;
        int nt = rem >> 5, lane = rem & 31;
        int t = lane & 3, g = lane >> 2;
        int u = nt * 8 + g;
        const float* wr = ((u < 128) ? (W1a + u * 192) : (W1g + (u - 128) * 192)) + 64 + grp * 16;
        g_B1h[id] = make_uint2(packh2(wr[2*t], wr[2*t+1]), packh2(wr[2*t+8], wr[2*t+9]));
    } else if (id < 12288) {                          // B2h: +W2a / -W2g
        int i = id - 8192;
        int grpG = i >> 8, rem = i & 255;
        int nt = rem >> 5, lane = rem & 31;
        int t = lane & 3, g = lane >> 2;
        int o = nt * 8 + g;
        if (grpG < 8) {
            const float* wr = W2a + o * 128 + grpG * 16;
            g_B2h[i] = make_uint2(packh2(wr[2*t], wr[2*t+1]), packh2(wr[2*t+8], wr[2*t+9]));
        } else {
            const float* wr = W2g + o * 128 + (grpG - 8) * 16;
            g_B2h[i] = make_uint2(packh2(-wr[2*t], -wr[2*t+1]), packh2(-wr[2*t+8], -wr[2*t+9]));
        }
    }
}

// ---------------- kA2: pack B3h + B4h ----------------
__global__ __launch_bounds__(512) void kA2(
    const float* __restrict__ Wih, const float* __restrict__ Whh)
{
    int id = blockIdx.x * 512 + threadIdx.x;
    if (id < 12288) {                                 // B3h: Whh[j][k]
        int grp = id / 1536, rem = id % 1536;
        int nt = rem >> 5, lane = rem & 31;
        int t = lane & 3, g = lane >> 2;
        int j = nt * 8 + g;
        const float* wr = Whh + j * 128 + grp * 16;
        g_B3h[id] = make_uint2(packh2(wr[2*t], wr[2*t+1]), packh2(wr[2*t+8], wr[2*t+9]));
    } else if (id < 18432) {                          // B4h: Wih[j][k], k<64
        int i = id - 12288;
        int grp = i / 1536, rem = i % 1536;
        int nt = rem >> 5, lane = rem & 31;
        int t = lane & 3, g = lane >> 2;
        int j = nt * 8 + g;
        const float* wr = Wih + j * 65 + grp * 16;
        g_B4h[i] = make_uint2(packh2(wr[2*t], wr[2*t+1]), packh2(wr[2*t+8], wr[2*t+9]));
    }
}

// ---------------- kA3: misc vectors ----------------
__global__ __launch_bounds__(512) void kA3(
    const float* __restrict__ x,
    const float* __restrict__ W1a, const float* __restrict__ b1a,
    const float* __restrict__ W1g, const float* __restrict__ b1g,
    const float* __restrict__ b2a, const float* __restrict__ b2g,
    const float* __restrict__ Wih,
    const float* __restrict__ bih, const float* __restrict__ bhh)
{
    int id = blockIdx.x * 512 + threadIdx.x;
    if (id < 256) {                                   // xc (exact fp32 x-fold)
        const float* W = (id < 128) ? W1a : W1g;
        const float* b = (id < 128) ? b1a : b1g;
        int j = id & 127;
        float s = b[j];
        const float* row = W + j * 192;
        #pragma unroll 8
        for (int k = 0; k < 64; k++) s += row[k] * x[k];
        g_xc[id] = s;
    } else if (id < 320) {
        int o = id - 256;
        g_b2d[o] = b2a[o] - b2g[o];
    } else if (id < 704) {
        int j = id - 320;
        g_wt[j] = Wih[j * 65 + 64];
    } else if (id < 960) {
        int j = id - 704;
        g_brz[j] = bih[j] + bhh[j];
    } else if (id < 1088) {
        int j = id - 960;
        g_bni[j] = bih[256 + j];
    } else if (id < 1216) {
        int j = id - 1088;
        g_bnh[j] = bhh[256 + j];
    }
}

// ---------------- Kernel B: fused pipeline, C1 half-buffer, direct nh stores ----------------
__global__ __launch_bounds__(TPB, 3) void kB(
    const float* __restrict__ hiddens,
    float* __restrict__ dout)
{
    extern __shared__ float sm[];
    __half* h_h   = (__half*)(sm + OFF_HH);
    __half* c1h   = (__half*)(sm + OFF_C1H);   // half of C1, reused for both K-halves
    __half* outh  = (__half*)(sm + OFF_OUTH);
    float*  t_s   = sm + OFF_T;
    float*  e_s   = sm + OFF_E;
    float*  xc_s  = sm + OFF_XC;
    float*  b2d_s = sm + OFF_B2D;
    float*  brz_s = sm + OFF_BRZ;
    float*  bni_s = sm + OFF_BNI;
    float*  bnh_s = sm + OFF_BNH;
    float*  wt_s  = sm + OFF_WT;

    const int tid  = threadIdx.x;
    const int blk  = blockIdx.x;
    const int w    = tid >> 5;            // 0..7
    const int lane = tid & 31;
    const int t4   = lane & 3;
    const int g    = lane >> 2;

    // ldmatrix per-lane byte offsets (row = lane&15, col-half = lane>>4)
    const unsigned sb   = (unsigned)__cvta_generic_to_shared(sm);
    const int lrow = lane & 15, lcol = lane >> 4;
    const unsigned hB   = sb + OFF_HH  * 4 + 2u * (lrow * HHP  + lcol * 8);
    const unsigned c1B  = sb + OFF_C1H * 4 + 2u * (lrow * C1HP + lcol * 8);
    const unsigned oB   = sb + OFF_OUTH* 4 + 2u * (lrow * OHP  + lcol * 8);

    const float* Hg = hiddens + (size_t)blk * MT * 128;
    float* NHg = dout + 65 + (size_t)blk * MT * 128;

    // ---- stage 0: load h tile (fp16) + constant tables ----
    #pragma unroll
    for (int i = tid; i < MT * 32; i += TPB) {       // 2048 float4
        float4 v = ((const float4*)Hg)[i];
        int c = i >> 5, k = (i & 31) << 2;
        unsigned* q = (unsigned*)(h_h + c * HHP + k);
        q[0] = packh2(v.x, v.y);
        q[1] = packh2(v.z, v.w);
    }
    { xc_s[tid] = g_xc[tid]; brz_s[tid] = g_brz[tid]; }
    if (tid < 64)  { b2d_s[tid] = g_b2d[tid]; }
    if (tid < 128) { bni_s[tid] = g_bni[tid]; bnh_s[tid] = g_bnh[tid]; }
    { if (tid < 128) wt_s[tid + 256] = g_wt[tid + 256]; wt_s[tid] = g_wt[tid]; }
    __syncthreads();

    // ---- stage 1+2 interleaved over K-halves (C1 half-buffer) ----
    const int mt2 = w & 3, ng2 = w >> 2;       // stage-2 warp roles
    float acc2[4][4];                          // stage-2 accumulators persist across phases
    #pragma unroll
    for (int n = 0; n < 4; n++)
        #pragma unroll
        for (int c = 0; c < 4; c++) acc2[n][c] = 0.f;

    #pragma unroll 1
    for (int p = 0; p < 2; p++) {
        // stage1 phase p: produce C1 units [128p, 128p+128) into c1h local cols [0,128)
        {
            float acc[4][2][4];                // [mt][n][c]
            #pragma unroll
            for (int m = 0; m < 4; m++)
                #pragma unroll
                for (int n = 0; n < 2; n++)
                    #pragma unroll
                    for (int c = 0; c < 4; c++) acc[m][n][c] = 0.f;
            #pragma unroll
            for (int grp = 0; grp < 8; grp++) {
                uint2 bv0 = g_B1h[(grp * 32 + 16 * p + 2 * w)     * 32 + lane];
                uint2 bv1 = g_B1h[(grp * 32 + 16 * p + 2 * w + 1) * 32 + lane];
                #pragma unroll
                for (int m = 0; m < 4; m++) {
                    unsigned a0, a1, a2, a3;
                    ldsm4(a0, a1, a2, a3, hB + 2u * (m * 16 * HHP + grp * 16));
                    mma16(acc[m][0], a0, a1, a2, a3, bv0.x, bv0.y);
                    mma16(acc[m][1], a0, a1, a2, a3, bv1.x, bv1.y);
                }
            }
            #pragma unroll
            for (int m = 0; m < 4; m++) {
                int r0 = m * 16 + g, r1 = r0 + 8;
                #pragma unroll
                for (int n = 0; n < 2; n++) {
                    int cbL = (2 * w + n) * 8 + 2 * t4;       // local col
                    int cbG = 128 * p + cbL;                  // global unit
                    float x0 = xc_s[cbG], x1 = xc_s[cbG + 1];
                    *(unsigned*)(c1h + r0 * C1HP + cbL) =
                        packh2(fmaxf(acc[m][n][0] + x0, 0.f), fmaxf(acc[m][n][1] + x1, 0.f));
                    *(unsigned*)(c1h + r1 * C1HP + cbL) =
                        packh2(fmaxf(acc[m][n][2] + x0, 0.f), fmaxf(acc[m][n][3] + x1, 0.f));
                }
            }
        }
        __syncthreads();

        // stage2 partial: K groups [8p, 8p+8)
        #pragma unroll
        for (int grpL = 0; grpL < 8; grpL++) {
            int grpG = 8 * p + grpL;
            unsigned a0, a1, a2, a3;
            ldsm4(a0, a1, a2, a3, c1B + 2u * (mt2 * 16 * C1HP + grpL * 16));
            #pragma unroll
            for (int ni = 0; ni < 4; ni++) {
                uint2 bv = g_B2h[(grpG * 8 + ng2 * 4 + ni) * 32 + lane];
                mma16(acc2[ni], a0, a1, a2, a3, bv.x, bv.y);
            }
        }
        __syncthreads();   // stage2 reads done -> safe to overwrite c1h (p=0) / all done (p=1)
    }

    // ---- write outh ----
    {
        int r0 = mt2 * 16 + g, r1 = r0 + 8;
        #pragma unroll
        for (int ni = 0; ni < 4; ni++) {
            int o = (ng2 * 4 + ni) * 8 + 2 * t4;
            float x0 = b2d_s[o], x1 = b2d_s[o + 1];
            *(unsigned*)(outh + r0 * OHP + o) = packh2(acc2[ni][0] + x0, acc2[ni][1] + x1);
            *(unsigned*)(outh + r1 * OHP + o) = packh2(acc2[ni][2] + x0, acc2[ni][3] + x1);
        }
    }
    __syncthreads();

    // ---- t/e (tid<64) — overlapped with GRU pass-0 mma of all warps ----
    if (tid < 64) {
        const unsigned* orow = (const unsigned*)(outh + tid * OHP);
        float s = 0.f;
        #pragma unroll
        for (int c = 0; c < 32; c++) {
            float2 f = __half22float2(*(const __half2*)(orow + c));
            s += f.x * f.x + f.y * f.y;
        }
        float tt = s * (1.f / 64.f);
        t_s[tid] = tt;
        e_s[tid] = expf(tt);
    }

    // ---- GRU: 4 passes, jt-major (B reuse back-to-back); direct global nh stores ----
    float hs[2][2] = {{0.f, 0.f}, {0.f, 0.f}};     // per-lane blk_h partials [jt][c]
    #pragma unroll 1
    for (int p = 0; p < 4; p++) {
        const int jt = p >> 1, mh = p & 1;
        float aR[2][4], aZ[2][4], aNh[2][4], aNi[2][4];   // [mi][c]  (32 acc live)
        #pragma unroll
        for (int m = 0; m < 2; m++)
            #pragma unroll
            for (int c = 0; c < 4; c++)
                { aR[m][c] = 0.f; aZ[m][c] = 0.f; aNh[m][c] = 0.f; aNi[m][c] = 0.f; }

        // h-side (K=128)
        #pragma unroll
        for (int grp = 0; grp < 8; grp++) {
            uint2 bR = g_B3h[(grp * 48 + 2 * w + jt)      * 32 + lane];
            uint2 bZ = g_B3h[(grp * 48 + 16 + 2 * w + jt) * 32 + lane];
            uint2 bN = g_B3h[(grp * 48 + 32 + 2 * w + jt) * 32 + lane];
            #pragma unroll
            for (int mi = 0; mi < 2; mi++) {
                unsigned a0, a1, a2, a3;
                ldsm4(a0, a1, a2, a3, hB + 2u * ((mh * 2 + mi) * 16 * HHP + grp * 16));
                mma16(aR[mi],  a0, a1, a2, a3, bR.x, bR.y);
                mma16(aZ[mi],  a0, a1, a2, a3, bZ.x, bZ.y);
                mma16(aNh[mi], a0, a1, a2, a3, bN.x, bN.y);
            }
        }
        // i-side (K=64): r,z accumulate on; n separate
        #pragma unroll
        for (int grp = 0; grp < 4; grp++) {
            uint2 bR = g_B4h[(grp * 48 + 2 * w + jt)      * 32 + lane];
            uint2 bZ = g_B4h[(grp * 48 + 16 + 2 * w + jt) * 32 + lane];
            uint2 bN = g_B4h[(grp * 48 + 32 + 2 * w + jt) * 32 + lane];
            #pragma unroll
            for (int mi = 0; mi < 2; mi++) {
                unsigned a0, a1, a2, a3;
                ldsm4(a0, a1, a2, a3, oB + 2u * ((mh * 2 + mi) * 16 * OHP + grp * 16));
                mma16(aR[mi],  a0, a1, a2, a3, bR.x, bR.y);
                mma16(aZ[mi],  a0, a1, a2, a3, bZ.x, bZ.y);
                mma16(aNi[mi], a0, a1, a2, a3, bN.x, bN.y);
            }
        }

        if (p == 0) __syncthreads();   // t_s/e_s ready

        // epilogue: nh straight to global (scalar pairs); accumulate blk_h partials
        {
            int j0 = 16 * w + jt * 8 + 2 * t4;
            float brzr0 = brz_s[j0],       brzr1 = brz_s[j0 + 1];
            float brzz0 = brz_s[128 + j0], brzz1 = brz_s[128 + j0 + 1];
            float bni0  = bni_s[j0],       bni1  = bni_s[j0 + 1];
            float bnh0  = bnh_s[j0],       bnh1  = bnh_s[j0 + 1];
            float wtr0 = wt_s[j0],        wtr1 = wt_s[j0 + 1];
            float wtz0 = wt_s[128 + j0],  wtz1 = wt_s[128 + j0 + 1];
            float wtn0 = wt_s[256 + j0],  wtn1 = wt_s[256 + j0 + 1];
            #pragma unroll
            for (int mi = 0; mi < 2; mi++) {
                int r0 = (mh * 2 + mi) * 16 + g, r1 = r0 + 8;
                float tv0 = t_s[r0], tv1 = t_s[r1];
                float2 hv0 = *(const float2*)(Hg + r0 * 128 + j0);
                float2 hv1 = *(const float2*)(Hg + r1 * 128 + j0);
                {
                    float r = sigmoid_f(aR[mi][0] + brzr0 + tv0 * wtr0);
                    float z = sigmoid_f(aZ[mi][0] + brzz0 + tv0 * wtz0);
                    float n = tanhf(aNi[mi][0] + tv0 * wtn0 + bni0 + r * (aNh[mi][0] + bnh0));
                    float v = (1.f - z) * n + z * hv0.x;
                    NHg[r0 * 128 + j0] = v;  hs[jt][0] += v;
                }
                {
                    float r = sigmoid_f(aR[mi][1] + brzr1 + tv0 * wtr1);
                    float z = sigmoid_f(aZ[mi][1] + brzz1 + tv0 * wtz1);
                    float n = tanhf(aNi[mi][1] + tv0 * wtn1 + bni1 + r * (aNh[mi][1] + bnh1));
                    float v = (1.f - z) * n + z * hv0.y;
                    NHg[r0 * 128 + j0 + 1] = v;  hs[jt][1] += v;
                }
                {
                    float r = sigmoid_f(aR[mi][2] + brzr0 + tv1 * wtr0);
                    float z = sigmoid_f(aZ[mi][2] + brzz0 + tv1 * wtz0);
                    float n = tanhf(aNi[mi][2] + tv1 * wtn0 + bni0 + r * (aNh[mi][2] + bnh0));
                    float v = (1.f - z) * n + z * hv1.x;
                    NHg[r1 * 128 + j0] = v;  hs[jt][0] += v;
                }
                {
                    float r = sigmoid_f(aR[mi][3] + brzr1 + tv1 * wtr1);
                    float z = sigmoid_f(aZ[mi][3] + brzz1 + tv1 * wtz1);
                    float n = tanhf(aNi[mi][3] + tv1 * wtn1 + bni1 + r * (aNh[mi][3] + bnh1));
                    float v = (1.f - z) * n + z * hv1.y;
                    NHg[r1 * 128 + j0 + 1] = v;  hs[jt][1] += v;
                }
            }
        }
    }

    // ---- blk_h partials via deterministic shfl reduction over g-lanes ----
    #pragma unroll
    for (int jt = 0; jt < 2; jt++) {
        float a = hs[jt][0], b = hs[jt][1];
        a += __shfl_xor_sync(0xffffffffu, a, 16); b += __shfl_xor_sync(0xffffffffu, b, 16);
        a += __shfl_xor_sync(0xffffffffu, a, 8);  b += __shfl_xor_sync(0xffffffffu, b, 8);
        a += __shfl_xor_sync(0xffffffffu, a, 4);  b += __shfl_xor_sync(0xffffffffu, b, 4);
        if (g == 0) {
            int j0 = 16 * w + jt * 8 + 2 * t4;
            g_blk_h[(size_t)blk * 128 + j0]     = a;
            g_blk_h[(size_t)blk * 128 + j0 + 1] = b;
        }
    }

    // ---- wout / t / e block partials (outh, t_s, e_s stable since pass-0 barrier) ----
    if (tid < 64) {
        float s = 0.f;
        #pragma unroll 8
        for (int c = 0; c < MT; c++) s += e_s[c] * __half2float(outh[c * OHP + tid]);
        g_blk_wout[(size_t)blk * 64 + tid] = s;
    } else if (tid == 64) {
        float s = 0.f;
        for (int c = 0; c < MT; c++) s += t_s[c];
        g_blk_t[blk] = s;
    } else if (tid == 96) {
        float s = 0.f;
        for (int c = 0; c < MT; c++) s += e_s[c];
        g_blk_e[blk] = s;
    }
}

// ---------------- Kernel C: global reductions + head ----------------
__global__ __launch_bounds__(1024) void kC(
    const float* __restrict__ Wo, const float* __restrict__ bo,
    float* __restrict__ dout)
{
    __shared__ float s_red[1024];
    __shared__ float s_red2[1024];
    __shared__ float s_comb[64];
    __shared__ float s_esum;
    const int tid = threadIdx.x;

    // faction sums: thread = (faction f, hidden j); 256 blocks per faction
    {
        int f = tid >> 7, j = tid & 127;
        const float* p = g_blk_h + (size_t)(f * 256) * 128 + j;
        float s = 0.f;
        #pragma unroll 8
        for (int b = 0; b < 256; b++) s += p[b * 128];
        g_fm[f * 128 + j] = s * (1.f / 16384.f);
        s_red[tid] = s;
    }
    __syncthreads();
    if (tid < 128) {
        float gg = 0.f;
        #pragma unroll
        for (int f = 0; f < 8; f++) gg += s_red[f * 128 + tid];
        g_go[tid] = gg * (1.f / (float)NCELLS);
    }
    __syncthreads();

    // weighted-out numerator: 16 chunks x 64 outputs, 128 blocks/chunk
    {
        int o = tid & 63, ch = tid >> 6;
        const float* p = g_blk_wout + (size_t)(ch * 128) * 64 + o;
        float s = 0.f;
        #pragma unroll 8
        for (int b = 0; b < 128; b++) s += p[b * 64];
        s_red[tid] = s;
    }
    __syncthreads();
    if (tid < 64) {
        float s = 0.f;
        #pragma unroll
        for (int ch = 0; ch < 16; ch++) s += s_red[ch * 64 + tid];
        s_comb[tid] = s;
    }
    __syncthreads();

    // exp-sum + t-sum (2 elements per thread, NBLK==2048)
    float se = 0.f, st = 0.f;
    #pragma unroll
    for (int i = tid; i < NBLK; i += 1024) { se += g_blk_e[i]; st += g_blk_t[i]; }
    s_red[tid]  = se;
    s_red2[tid] = st;
    __syncthreads();
    for (int off = 512; off > 0; off >>= 1) {
        if (tid < off) { s_red[tid] += s_red[tid + off]; s_red2[tid] += s_red2[tid + off]; }
        __syncthreads();
    }
    if (tid == 0) {
        s_esum = s_red[0];
        dout[64] = s_red2[0] * (1.f / (float)NCELLS);
    }
    __syncthreads();

    if (tid < 64) s_comb[tid] *= (1.f / s_esum);
    __syncthreads();
    if (tid < 64) {
        float p = bo[tid];
        const float* wr = Wo + tid * 64;
        #pragma unroll 8
        for (int o = 0; o < 64; o++) p += wr[o] * s_comb[o];
        dout[tid] = p;
    }
}

// ---------------- Kernel D: faction sync, float4 RMW with scalar peel ----------------
// nh = dout+65; nh+3 is 16B-aligned. Chunks cover e in [3, 16777215); peel e=0,1,2 and e=16777215.
__global__ __launch_bounds__(512) void kD(float* __restrict__ nh, const void* __restrict__ stepPtr)
{
    int iv = *(const int*)stepPtr;
    int step = (iv >= 0 && iv < 1000000) ? iv : (int)(*(const float*)stepPtr);
    const bool debate = (step > 5);

    if (blockIdx.x == 0 && threadIdx.x < 4) {
        unsigned e = (threadIdx.x < 3) ? threadIdx.x : 16777215u;
        unsigned cell = e >> 7, j = e & 127u;
        unsigned f = cell >> 14, pos = cell & 16383u;
        float v = nh[e];
        v = 0.85f * v + 0.15f * g_fm[f * 128 + j];
        if (debate && pos < 4096u) v = 0.85f * v + 0.15f * g_go[j];
        nh[e] = v;
    }

    float4* nh4 = (float4*)(nh + 3);
    unsigned base = blockIdx.x * 512u + threadIdx.x;
    const unsigned stride = 2048u * 512u;
    #pragma unroll
    for (int r = 0; r < 4; r++) {
        unsigned q = base + (unsigned)r * stride;
        if (q < 4194303u) {
            float4 v = nh4[q];
            float va[4] = {v.x, v.y, v.z, v.w};
            unsigned e0 = 3u + 4u * q;
            #pragma unroll
            for (int i = 0; i < 4; i++) {
                unsigned e = e0 + (unsigned)i;
                unsigned cell = e >> 7, j = e & 127u;
                unsigned f = cell >> 14, pos = cell & 16383u;
                float val = va[i];
                val = 0.85f * val + 0.15f * g_fm[f * 128 + j];
                if (debate && pos < 4096u) val = 0.85f * val + 0.15f * g_go[j];
                va[i] = val;
            }
            nh4[q] = make_float4(va[0], va[1], va[2], va[3]);
        }
    }
}

// ---------------- launcher ----------------
extern "C" void kernel_launch(void* const* d_in, const int* in_sizes, int n_in,
                              void* d_out, int out_size)
{
    const float* x    = (const float*)d_in[0];
    const float* hid  = (const float*)d_in[1];
    const float* W1a  = (const float*)d_in[2];
    const float* b1a  = (const float*)d_in[3];
    const float* W2a  = (const float*)d_in[4];
    const float* b2a  = (const float*)d_in[5];
    const float* W1g  = (const float*)d_in[6];
    const float* b1g  = (const float*)d_in[7];
    const float* W2g  = (const float*)d_in[8];
    const float* b2g  = (const float*)d_in[9];
    const float* Wih  = (const float*)d_in[10];
    const float* Whh  = (const float*)d_in[11];
    const float* bih  = (const float*)d_in[12];
    const float* bhh  = (const float*)d_in[13];
    const float* Wo   = (const float*)d_in[14];
    const float* bo   = (const float*)d_in[15];
    const void*  step = (n_in > 16) ? (const void*)d_in[16] : (const void*)d_in[15];

    float* out = (float*)d_out;
    float* nh  = out + 65;

    cudaFuncSetAttribute(kB, cudaFuncAttributeMaxDynamicSharedMemorySize, SMEM_KB_BYTES);

    kA1<<<24, 512>>>(W1a, W1g, W2a, W2g);
    kA2<<<36, 512>>>(Wih, Whh);
    kA3<<<3, 512>>>(x, W1a, b1a, W1g, b1g, b2a, b2g, Wih, bih, bhh);
    kB<<<NBLK, TPB, SMEM_KB_BYTES>>>(hid, out);
    kC<<<1, 1024>>>(Wo, bo, out);
    kD<<<2048, 512>>>(nh, step);
}

// round 14
// speedup vs baseline: 1.0664x; 1.0664x over previous
#include <cuda_runtime.h>
#include <cuda_fp16.h>
#include <stdint.h>
#include <math.h>

// ---------------- problem constants ----------------
#define NCELLS 131072
#define MT   64
#define TPB  256
#define NBLK (NCELLS / MT)   // 2048

// ---------------- smem layout (float offsets) ----------------
// all half pitches are ≡ 16 (mod 128) BYTES -> ldmatrix 8-row groups conflict-free
#define HHP   136            // h_h half pitch   (272 B)
#define C1HP  264            // C1h half pitch   (528 B)
#define OHP   72             // out_h half pitch (144 B)
#define NHP   132            // nh fp32 pitch (aliases C1 region exactly: 64*132 = 64*264/2)

#define OFF_HH   0                        // 64*136 h = 4352 floats
#define OFF_C1H  4352                     // 64*264 h = 8448 floats (nh fp32 alias 64*132)
#define OFF_OUTH 12800                    // 64*72 h  = 2304 floats
#define OFF_T    15104                    // 64
#define OFF_E    15168                    // 64
#define OFF_XC   15232                    // 256
#define OFF_B2D  15488                    // 64
#define OFF_BRZ  15552                    // 256
#define OFF_BNI  15808                    // 128
#define OFF_BNH  15936                    // 128
#define OFF_WT   16064                    // 384
#define SMEM_KB_FLOATS 16448
#define SMEM_KB_BYTES  (SMEM_KB_FLOATS * 4)   // 65792 B -> 3 blocks/SM

// ---------------- device scratch (static, allocation-free) ----------------
__device__ uint2 g_B1h[8 * 32 * 32];     // stage1  K=128,N=256
__device__ uint2 g_B2h[16 * 8 * 32];     // stage2  K=256,N=64 (sign-folded)
__device__ uint2 g_B3h[8 * 48 * 32];     // GRU Whh K=128,N=384
__device__ uint2 g_B4h[4 * 48 * 32];     // GRU Wih K=64, N=384
__device__ float g_xc[256];
__device__ float g_b2d[64];
__device__ float g_brz[256];
__device__ float g_bni[128];
__device__ float g_bnh[128];
__device__ float g_wt[384];
__device__ float g_blk_t[NBLK];
__device__ float g_blk_e[NBLK];
__device__ float g_blk_wout[NBLK * 64];
__device__ float g_blk_h[NBLK * 128];
__device__ float g_fs[8 * 128];          // raw faction sums (kC1 -> kC2)
__device__ float g_woutp[16 * 64];       // wout chunk partials (kC1 -> kC2)
__device__ float g_fm[8 * 128];
__device__ float g_go[128];

// ---------------- helpers ----------------
__device__ __forceinline__ unsigned packh2(float lo, float hi) {
    __half2 h = __floats2half2_rn(lo, hi);
    return *(unsigned*)&h;
}
__device__ __forceinline__ void mma16(float* c,
    unsigned a0, unsigned a1, unsigned a2, unsigned a3,
    unsigned b0, unsigned b1)
{
    asm volatile(
        "mma.sync.aligned.m16n8k16.row.col.f32.f16.f16.f32 "
        "{%0,%1,%2,%3},{%4,%5,%6,%7},{%8,%9},{%0,%1,%2,%3};"
        : "+f"(c[0]), "+f"(c[1]), "+f"(c[2]), "+f"(c[3])
        : "r"(a0), "r"(a1), "r"(a2), "r"(a3), "r"(b0), "r"(b1));
}
__device__ __forceinline__ void ldsm4(unsigned& a0, unsigned& a1, unsigned& a2, unsigned& a3,
                                      unsigned addr)
{
    asm volatile("ldmatrix.sync.aligned.m8n8.x4.shared.b16 {%0,%1,%2,%3}, [%4];"
                 : "=r"(a0), "=r"(a1), "=r"(a2), "=r"(a3) : "r"(addr));
}
__device__ __forceinline__ float sigmoid_f(float x) {
    return 1.f / (1.f + __expf(-x));
}

// ---------------- kA1: pack B1h + B2h ----------------
__global__ __launch_bounds__(512) void kA1(
    const float* __restrict__ W1a, const float* __restrict__ W1g,
    const float* __restrict__ W2a, const float* __restrict__ W2g)
{
    int id = blockIdx.x * 512 + threadIdx.x;
    if (id < 8192) {                                  // B1h: B[k][u]=W1[u][64+k]
        int grp = id >> 10, rem = id & 1023;
        int nt = rem >> 5, lane = rem & 31;
        int t = lane & 3, g = lane >> 2;
        int u = nt * 8 + g;
        const float* wr = ((u < 128) ? (W1a + u * 192) : (W1g + (u - 128) * 192)) + 64 + grp * 16;
        g_B1h[id] = make_uint2(packh2(wr[2*t], wr[2*t+1]), packh2(wr[2*t+8], wr[2*t+9]));
    } else if (id < 12288) {                          // B2h: +W2a / -W2g
        int i = id - 8192;
        int grpG = i >> 8, rem = i & 255;
        int nt = rem >> 5, lane = rem & 31;
        int t = lane & 3, g = lane >> 2;
        int o = nt * 8 + g;
        if (grpG < 8) {
            const float* wr = W2a + o * 128 + grpG * 16;
            g_B2h[i] = make_uint2(packh2(wr[2*t], wr[2*t+1]), packh2(wr[2*t+8], wr[2*t+9]));
        } else {
            const float* wr = W2g + o * 128 + (grpG - 8) * 16;
            g_B2h[i] = make_uint2(packh2(-wr[2*t], -wr[2*t+1]), packh2(-wr[2*t+8], -wr[2*t+9]));
        }
    }
}

// ---------------- kA2: pack B3h + B4h ----------------
__global__ __launch_bounds__(512) void kA2(
    const float* __restrict__ Wih, const float* __restrict__ Whh)
{
    int id = blockIdx.x * 512 + threadIdx.x;
    if (id < 12288) {                                 // B3h: Whh[j][k]
        int grp = id / 1536, rem = id % 1536;
        int nt = rem >> 5, lane = rem & 31;
        int t = lane & 3, g = lane >> 2;
        int j = nt * 8 + g;
        const float* wr = Whh + j * 128 + grp * 16;
        g_B3h[id] = make_uint2(packh2(wr[2*t], wr[2*t+1]), packh2(wr[2*t+8], wr[2*t+9]));
    } else if (id < 18432) {                          // B4h: Wih[j][k], k<64
        int i = id - 12288;
        int grp = i / 1536, rem = i % 1536;
        int nt = rem >> 5, lane = rem & 31;
        int t = lane & 3, g = lane >> 2;
        int j = nt * 8 + g;
        const float* wr = Wih + j * 65 + grp * 16;
        g_B4h[i] = make_uint2(packh2(wr[2*t], wr[2*t+1]), packh2(wr[2*t+8], wr[2*t+9]));
    }
}

// ---------------- kA3: misc vectors ----------------
__global__ __launch_bounds__(512) void kA3(
    const float* __restrict__ x,
    const float* __restrict__ W1a, const float* __restrict__ b1a,
    const float* __restrict__ W1g, const float* __restrict__ b1g,
    const float* __restrict__ b2a, const float* __restrict__ b2g,
    const float* __restrict__ Wih,
    const float* __restrict__ bih, const float* __restrict__ bhh)
{
    int id = blockIdx.x * 512 + threadIdx.x;
    if (id < 256) {                                   // xc (exact fp32 x-fold)
        const float* W = (id < 128) ? W1a : W1g;
        const float* b = (id < 128) ? b1a : b1g;
        int j = id & 127;
        float s = b[j];
        const float* row = W + j * 192;
        #pragma unroll 8
        for (int k = 0; k < 64; k++) s += row[k] * x[k];
        g_xc[id] = s;
    } else if (id < 320) {
        int o = id - 256;
        g_b2d[o] = b2a[o] - b2g[o];
    } else if (id < 704) {
        int j = id - 320;
        g_wt[j] = Wih[j * 65 + 64];
    } else if (id < 960) {
        int j = id - 704;
        g_brz[j] = bih[j] + bhh[j];
    } else if (id < 1088) {
        int j = id - 960;
        g_bni[j] = bih[256 + j];
    } else if (id < 1216) {
        int j = id - 1088;
        g_bnh[j] = bhh[256 + j];
    }
}

// ---------------- Kernel B: fused pipeline, 256thr/64cells, 3 blocks/SM (R12 layout) ----------------
__global__ __launch_bounds__(TPB, 3) void kB(
    const float* __restrict__ hiddens,
    float* __restrict__ dout)
{
    extern __shared__ float sm[];
    __half* h_h   = (__half*)(sm + OFF_HH);
    __half* c1h   = (__half*)(sm + OFF_C1H);
    float*  nh_s  = sm + OFF_C1H;        // aliases c1h after stage 2
    __half* outh  = (__half*)(sm + OFF_OUTH);
    float*  t_s   = sm + OFF_T;
    float*  e_s   = sm + OFF_E;
    float*  xc_s  = sm + OFF_XC;
    float*  b2d_s = sm + OFF_B2D;
    float*  brz_s = sm + OFF_BRZ;
    float*  bni_s = sm + OFF_BNI;
    float*  bnh_s = sm + OFF_BNH;
    float*  wt_s  = sm + OFF_WT;

    const int tid  = threadIdx.x;
    const int blk  = blockIdx.x;
    const int w    = tid >> 5;            // 0..7
    const int lane = tid & 31;
    const int t4   = lane & 3;
    const int g    = lane >> 2;

    // ldmatrix per-lane byte offsets (row = lane&15, col-half = lane>>4)
    const unsigned sb   = (unsigned)__cvta_generic_to_shared(sm);
    const int lrow = lane & 15, lcol = lane >> 4;
    const unsigned hB   = sb + OFF_HH  * 4 + 2u * (lrow * HHP  + lcol * 8);
    const unsigned c1B  = sb + OFF_C1H * 4 + 2u * (lrow * C1HP + lcol * 8);
    const unsigned oB   = sb + OFF_OUTH* 4 + 2u * (lrow * OHP  + lcol * 8);

    const float* Hg = hiddens + (size_t)blk * MT * 128;

    // ---- stage 0: load h tile (fp16) + constant tables ----
    #pragma unroll
    for (int i = tid; i < MT * 32; i += TPB) {       // 2048 float4
        float4 v = ((const float4*)Hg)[i];
        int c = i >> 5, k = (i & 31) << 2;
        unsigned* q = (unsigned*)(h_h + c * HHP + k);
        q[0] = packh2(v.x, v.y);
        q[1] = packh2(v.z, v.w);
    }
    { xc_s[tid] = g_xc[tid]; brz_s[tid] = g_brz[tid]; }
    if (tid < 64)  { b2d_s[tid] = g_b2d[tid]; }
    if (tid < 128) { bni_s[tid] = g_bni[tid]; bnh_s[tid] = g_bnh[tid]; }
    { if (tid < 128) wt_s[tid + 256] = g_wt[tid + 256]; wt_s[tid] = g_wt[tid]; }
    __syncthreads();

    // ---- stage 1: C1[64x256] = relu(h @ B1 + xc); two n-half passes (32 acc live) ----
    #pragma unroll 1
    for (int nh2 = 0; nh2 < 2; nh2++) {
        float acc[4][2][4];                          // [mt][n][c]
        #pragma unroll
        for (int m = 0; m < 4; m++)
            #pragma unroll
            for (int n = 0; n < 2; n++)
                #pragma unroll
                for (int c = 0; c < 4; c++) acc[m][n][c] = 0.f;
        #pragma unroll
        for (int grp = 0; grp < 8; grp++) {
            uint2 bv0 = g_B1h[(grp * 32 + 4 * w + 2 * nh2)     * 32 + lane];
            uint2 bv1 = g_B1h[(grp * 32 + 4 * w + 2 * nh2 + 1) * 32 + lane];
            #pragma unroll
            for (int m = 0; m < 4; m++) {
                unsigned a0, a1, a2, a3;
                ldsm4(a0, a1, a2, a3, hB + 2u * (m * 16 * HHP + grp * 16));
                mma16(acc[m][0], a0, a1, a2, a3, bv0.x, bv0.y);
                mma16(acc[m][1], a0, a1, a2, a3, bv1.x, bv1.y);
            }
        }
        #pragma unroll
        for (int m = 0; m < 4; m++) {
            int r0 = m * 16 + g, r1 = r0 + 8;
            #pragma unroll
            for (int n = 0; n < 2; n++) {
                int cb = (4 * w + 2 * nh2 + n) * 8 + 2 * t4;
                float x0 = xc_s[cb], x1 = xc_s[cb + 1];
                *(unsigned*)(c1h + r0 * C1HP + cb) =
                    packh2(fmaxf(acc[m][n][0] + x0, 0.f), fmaxf(acc[m][n][1] + x1, 0.f));
                *(unsigned*)(c1h + r1 * C1HP + cb) =
                    packh2(fmaxf(acc[m][n][2] + x0, 0.f), fmaxf(acc[m][n][3] + x1, 0.f));
            }
        }
    }
    __syncthreads();

    // ---- stage 2: out[64x64] = C1 @ B2 + b2d; warp = (mt = w&3, ng = w>>2), full K=256 ----
    {
        const int mt = w & 3, ng = w >> 2;
        float acc[4][4];
        #pragma unroll
        for (int n = 0; n < 4; n++)
            #pragma unroll
            for (int c = 0; c < 4; c++) acc[n][c] = 0.f;
        #pragma unroll
        for (int grpG = 0; grpG < 16; grpG++) {
            unsigned a0, a1, a2, a3;
            ldsm4(a0, a1, a2, a3, c1B + 2u * (mt * 16 * C1HP + grpG * 16));
            #pragma unroll
            for (int ni = 0; ni < 4; ni++) {
                uint2 bv = g_B2h[(grpG * 8 + ng * 4 + ni) * 32 + lane];
                mma16(acc[ni], a0, a1, a2, a3, bv.x, bv.y);
            }
        }
        int r0 = mt * 16 + g, r1 = r0 + 8;
        #pragma unroll
        for (int ni = 0; ni < 4; ni++) {
            int o = (ng * 4 + ni) * 8 + 2 * t4;
            float x0 = b2d_s[o], x1 = b2d_s[o + 1];
            *(unsigned*)(outh + r0 * OHP + o) = packh2(acc[ni][0] + x0, acc[ni][1] + x1);
            *(unsigned*)(outh + r1 * OHP + o) = packh2(acc[ni][2] + x0, acc[ni][3] + x1);
        }
    }
    __syncthreads();

    // ---- t/e (tid<64) — overlapped with GRU pass-0 mma of all warps ----
    if (tid < 64) {
        const unsigned* orow = (const unsigned*)(outh + tid * OHP);
        float s = 0.f;
        #pragma unroll
        for (int c = 0; c < 32; c++) {
            float2 f = __half22float2(*(const __half2*)(orow + c));
            s += f.x * f.x + f.y * f.y;
        }
        float tt = s * (1.f / 64.f);
        t_s[tid] = tt;
        e_s[tid] = expf(tt);
    }

    // ---- GRU: 4 passes (m-half mh, j-tile jt); warp's j-slice = [16w+8jt, 16w+8jt+8) ----
    #pragma unroll 1
    for (int p = 0; p < 4; p++) {
        const int mh = p >> 1, jt = p & 1;
        float aR[2][4], aZ[2][4], aNh[2][4], aNi[2][4];   // [mi][c]  (32 acc live)
        #pragma unroll
        for (int m = 0; m < 2; m++)
            #pragma unroll
            for (int c = 0; c < 4; c++)
                { aR[m][c] = 0.f; aZ[m][c] = 0.f; aNh[m][c] = 0.f; aNi[m][c] = 0.f; }

        // h-side (K=128)
        #pragma unroll
        for (int grp = 0; grp < 8; grp++) {
            uint2 bR = g_B3h[(grp * 48 + 2 * w + jt)      * 32 + lane];
            uint2 bZ = g_B3h[(grp * 48 + 16 + 2 * w + jt) * 32 + lane];
            uint2 bN = g_B3h[(grp * 48 + 32 + 2 * w + jt) * 32 + lane];
            #pragma unroll
            for (int mi = 0; mi < 2; mi++) {
                unsigned a0, a1, a2, a3;
                ldsm4(a0, a1, a2, a3, hB + 2u * ((mh * 2 + mi) * 16 * HHP + grp * 16));
                mma16(aR[mi],  a0, a1, a2, a3, bR.x, bR.y);
                mma16(aZ[mi],  a0, a1, a2, a3, bZ.x, bZ.y);
                mma16(aNh[mi], a0, a1, a2, a3, bN.x, bN.y);
            }
        }
        // i-side (K=64): r,z accumulate on; n separate
        #pragma unroll
        for (int grp = 0; grp < 4; grp++) {
            uint2 bR = g_B4h[(grp * 48 + 2 * w + jt)      * 32 + lane];
            uint2 bZ = g_B4h[(grp * 48 + 16 + 2 * w + jt) * 32 + lane];
            uint2 bN = g_B4h[(grp * 48 + 32 + 2 * w + jt) * 32 + lane];
            #pragma unroll
            for (int mi = 0; mi < 2; mi++) {
                unsigned a0, a1, a2, a3;
                ldsm4(a0, a1, a2, a3, oB + 2u * ((mh * 2 + mi) * 16 * OHP + grp * 16));
                mma16(aR[mi],  a0, a1, a2, a3, bR.x, bR.y);
                mma16(aZ[mi],  a0, a1, a2, a3, bZ.x, bZ.y);
                mma16(aNi[mi], a0, a1, a2, a3, bN.x, bN.y);
            }
        }

        if (p == 0) __syncthreads();   // t_s/e_s ready; stage-2 c1h reads complete -> nh alias safe

        // epilogue: nh into staging (c1h alias); exact fp32 h re-read from global (L2-hot)
        {
            int j0 = 16 * w + jt * 8 + 2 * t4;
            float brzr0 = brz_s[j0],       brzr1 = brz_s[j0 + 1];
            float brzz0 = brz_s[128 + j0], brzz1 = brz_s[128 + j0 + 1];
            float bni0  = bni_s[j0],       bni1  = bni_s[j0 + 1];
            float bnh0  = bnh_s[j0],       bnh1  = bnh_s[j0 + 1];
            float wtr0 = wt_s[j0],        wtr1 = wt_s[j0 + 1];
            float wtz0 = wt_s[128 + j0],  wtz1 = wt_s[128 + j0 + 1];
            float wtn0 = wt_s[256 + j0],  wtn1 = wt_s[256 + j0 + 1];
            #pragma unroll
            for (int mi = 0; mi < 2; mi++) {
                int r0 = (mh * 2 + mi) * 16 + g, r1 = r0 + 8;
                float tv0 = t_s[r0], tv1 = t_s[r1];
                float2 hv0 = *(const float2*)(Hg + r0 * 128 + j0);
                float2 hv1 = *(const float2*)(Hg + r1 * 128 + j0);
                {
                    float r = sigmoid_f(aR[mi][0] + brzr0 + tv0 * wtr0);
                    float z = sigmoid_f(aZ[mi][0] + brzz0 + tv0 * wtz0);
                    float n = tanhf(aNi[mi][0] + tv0 * wtn0 + bni0 + r * (aNh[mi][0] + bnh0));
                    nh_s[r0 * NHP + j0] = (1.f - z) * n + z * hv0.x;
                }
                {
                    float r = sigmoid_f(aR[mi][1] + brzr1 + tv0 * wtr1);
                    float z = sigmoid_f(aZ[mi][1] + brzz1 + tv0 * wtz1);
                    float n = tanhf(aNi[mi][1] + tv0 * wtn1 + bni1 + r * (aNh[mi][1] + bnh1));
                    nh_s[r0 * NHP + j0 + 1] = (1.f - z) * n + z * hv0.y;
                }
                {
                    float r = sigmoid_f(aR[mi][2] + brzr0 + tv1 * wtr0);
                    float z = sigmoid_f(aZ[mi][2] + brzz0 + tv1 * wtz0);
                    float n = tanhf(aNi[mi][2] + tv1 * wtn0 + bni0 + r * (aNh[mi][2] + bnh0));
                    nh_s[r1 * NHP + j0] = (1.f - z) * n + z * hv1.x;
                }
                {
                    float r = sigmoid_f(aR[mi][3] + brzr1 + tv1 * wtr1);
                    float z = sigmoid_f(aZ[mi][3] + brzz1 + tv1 * wtz1);
                    float n = tanhf(aNi[mi][3] + tv1 * wtn1 + bni1 + r * (aNh[mi][3] + bnh1));
                    nh_s[r1 * NHP + j0 + 1] = (1.f - z) * n + z * hv1.y;
                }
            }
        }
    }
    __syncthreads();

    // ---- store new_h (pre-sync) coalesced; block partials ----
    float* NH = dout + 65 + (size_t)blk * MT * 128;
    #pragma unroll
    for (int i = tid; i < MT * 128; i += TPB) {
        int c = i >> 7, k = i & 127;
        NH[i] = nh_s[c * NHP + k];
    }
    if (tid < 128) {
        float s = 0.f;
        #pragma unroll 8
        for (int c = 0; c < MT; c++) s += nh_s[c * NHP + tid];
        g_blk_h[(size_t)blk * 128 + tid] = s;
    }
    if (tid < 64) {
        float s = 0.f;
        #pragma unroll 8
        for (int c = 0; c < MT; c++) s += e_s[c] * __half2float(outh[c * OHP + tid]);
        g_blk_wout[(size_t)blk * 64 + tid] = s;
    } else if (tid == 64) {
        float s = 0.f;
        for (int c = 0; c < MT; c++) s += t_s[c];
        g_blk_t[blk] = s;
    } else if (tid == 96) {
        float s = 0.f;
        for (int c = 0; c < MT; c++) s += e_s[c];
        g_blk_e[blk] = s;
    }
}

// ---------------- kC1: parallel partial reductions (24 blocks) ----------------
__global__ __launch_bounds__(128) void kC1(void)
{
    const int b = blockIdx.x;
    const int tid = threadIdx.x;
    if (b < 8) {
        // faction sums: faction b, hidden j=tid; 256 kB-blocks per faction
        const float* p = g_blk_h + (size_t)(b * 256) * 128 + tid;
        float s = 0.f;
        #pragma unroll 8
        for (int k = 0; k < 256; k++) s += p[k * 128];
        g_fs[b * 128 + tid] = s;
        g_fm[b * 128 + tid] = s * (1.f / 16384.f);
    } else if (tid < 64) {
        // wout chunk (b-8): 128 kB-blocks x 64 outputs
        int ch = b - 8;
        const float* p = g_blk_wout + (size_t)(ch * 128) * 64 + tid;
        float s = 0.f;
        #pragma unroll 8
        for (int k = 0; k < 128; k++) s += p[k * 64];
        g_woutp[ch * 64 + tid] = s;
    }
}

// ---------------- kC2: combine partials + head (1 block) ----------------
__global__ __launch_bounds__(1024) void kC2(
    const float* __restrict__ Wo, const float* __restrict__ bo,
    float* __restrict__ dout)
{
    __shared__ float s_red[1024];
    __shared__ float s_red2[1024];
    __shared__ float s_comb[64];
    __shared__ float s_esum;
    const int tid = threadIdx.x;

    if (tid < 128) {
        float gg = 0.f;
        #pragma unroll
        for (int f = 0; f < 8; f++) gg += g_fs[f * 128 + tid];
        g_go[tid] = gg * (1.f / (float)NCELLS);
    }
    if (tid < 64) {
        float s = 0.f;
        #pragma unroll
        for (int ch = 0; ch < 16; ch++) s += g_woutp[ch * 64 + tid];
        s_comb[tid] = s;
    }

    // exp-sum + t-sum (2 elements per thread, NBLK==2048)
    float se = 0.f, st = 0.f;
    #pragma unroll
    for (int i = tid; i < NBLK; i += 1024) { se += g_blk_e[i]; st += g_blk_t[i]; }
    s_red[tid]  = se;
    s_red2[tid] = st;
    __syncthreads();
    for (int off = 512; off > 0; off >>= 1) {
        if (tid < off) { s_red[tid] += s_red[tid + off]; s_red2[tid] += s_red2[tid + off]; }
        __syncthreads();
    }
    if (tid == 0) {
        s_esum = s_red[0];
        dout[64] = s_red2[0] * (1.f / (float)NCELLS);
    }
    __syncthreads();

    if (tid < 64) s_comb[tid] *= (1.f / s_esum);
    __syncthreads();
    if (tid < 64) {
        float p = bo[tid];
        const float* wr = Wo + tid * 64;
        #pragma unroll 8
        for (int o = 0; o < 64; o++) p += wr[o] * s_comb[o];
        dout[tid] = p;
    }
}

// ---------------- Kernel D: faction sync, float4 RMW with scalar peel ----------------
// nh = dout+65; nh+3 is 16B-aligned. Chunks cover e in [3, 16777215); peel e=0,1,2 and e=16777215.
__global__ __launch_bounds__(512) void kD(float* __restrict__ nh, const void* __restrict__ stepPtr)
{
    int iv = *(const int*)stepPtr;
    int step = (iv >= 0 && iv < 1000000) ? iv : (int)(*(const float*)stepPtr);
    const bool debate = (step > 5);

    if (blockIdx.x == 0 && threadIdx.x < 4) {
        unsigned e = (threadIdx.x < 3) ? threadIdx.x : 16777215u;
        unsigned cell = e >> 7, j = e & 127u;
        unsigned f = cell >> 14, pos = cell & 16383u;
        float v = nh[e];
        v = 0.85f * v + 0.15f * g_fm[f * 128 + j];
        if (debate && pos < 4096u) v = 0.85f * v + 0.15f * g_go[j];
        nh[e] = v;
    }

    float4* nh4 = (float4*)(nh + 3);
    unsigned base = blockIdx.x * 512u + threadIdx.x;
    const unsigned stride = 2048u * 512u;
    #pragma unroll
    for (int r = 0; r < 4; r++) {
        unsigned q = base + (unsigned)r * stride;
        if (q < 4194303u) {
            float4 v = nh4[q];
            float va[4] = {v.x, v.y, v.z, v.w};
            unsigned e0 = 3u + 4u * q;
            #pragma unroll
            for (int i = 0; i < 4; i++) {
                unsigned e = e0 + (unsigned)i;
                unsigned cell = e >> 7, j = e & 127u;
                unsigned f = cell >> 14, pos = cell & 16383u;
                float val = va[i];
                val = 0.85f * val + 0.15f * g_fm[f * 128 + j];
                if (debate && pos < 4096u) val = 0.85f * val + 0.15f * g_go[j];
                va[i] = val;
            }
            nh4[q] = make_float4(va[0], va[1], va[2], va[3]);
        }
    }
}

// ---------------- launcher ----------------
extern "C" void kernel_launch(void* const* d_in, const int* in_sizes, int n_in,
                              void* d_out, int out_size)
{
    const float* x    = (const float*)d_in[0];
    const float* hid  = (const float*)d_in[1];
    const float* W1a  = (const float*)d_in[2];
    const float* b1a  = (const float*)d_in[3];
    const float* W2a  = (const float*)d_in[4];
    const float* b2a  = (const float*)d_in[5];
    const float* W1g  = (const float*)d_in[6];
    const float* b1g  = (const float*)d_in[7];
    const float* W2g  = (const float*)d_in[8];
    const float* b2g  = (const float*)d_in[9];
    const float* Wih  = (const float*)d_in[10];
    const float* Whh  = (const float*)d_in[11];
    const float* bih  = (const float*)d_in[12];
    const float* bhh  = (const float*)d_in[13];
    const float* Wo   = (const float*)d_in[14];
    const float* bo   = (const float*)d_in[15];
    const void*  step = (n_in > 16) ? (const void*)d_in[16] : (const void*)d_in[15];

    float* out = (float*)d_out;
    float* nh  = out + 65;

    cudaFuncSetAttribute(kB, cudaFuncAttributeMaxDynamicSharedMemorySize, SMEM_KB_BYTES);

    kA1<<<24, 512>>>(W1a, W1g, W2a, W2g);
    kA2<<<36, 512>>>(Wih, Whh);
    kA3<<<3, 512>>>(x, W1a, b1a, W1g, b1g, b2a, b2g, Wih, bih, bhh);
    kB<<<NBLK, TPB, SMEM_KB_BYTES>>>(hid, out);
    kC1<<<24, 128>>>();
    kC2<<<1, 1024>>>(Wo, bo, out);
    kD<<<2048, 512>>>(nh, step);
}

// round 15
// speedup vs baseline: 1.0799x; 1.0127x over previous
#include <cuda_runtime.h>
#include <cuda_fp16.h>
#include <stdint.h>
#include <math.h>

// ---------------- problem constants ----------------
#define NCELLS 131072
#define MT   64
#define TPB  256
#define NBLK (NCELLS / MT)   // 2048

// ---------------- smem layout (float offsets) ----------------
// all half pitches are ≡ 16 (mod 128) BYTES -> ldmatrix 8-row groups conflict-free
#define HHP   136            // h_h half pitch   (272 B)
#define C1HP  264            // C1h half pitch   (528 B)
#define OHP   72             // out_h half pitch (144 B)
#define NHP   132            // nh fp32 pitch (aliases C1 region exactly: 64*132 = 64*264/2)

#define OFF_HH   0                        // 64*136 h = 4352 floats
#define OFF_C1H  4352                     // 64*264 h = 8448 floats (nh fp32 alias 64*132)
#define OFF_OUTH 12800                    // 64*72 h  = 2304 floats
#define OFF_T    15104                    // 64
#define OFF_E    15168                    // 64
#define OFF_XC   15232                    // 256
#define OFF_B2D  15488                    // 64
#define OFF_BRZ  15552                    // 256
#define OFF_BNI  15808                    // 128
#define OFF_BNH  15936                    // 128
#define OFF_WT   16064                    // 384
#define SMEM_KB_FLOATS 16448
#define SMEM_KB_BYTES  (SMEM_KB_FLOATS * 4)   // 65792 B -> 3 blocks/SM

// ---------------- device scratch (static, allocation-free) ----------------
__device__ uint2 g_B1h[8 * 32 * 32];     // stage1  K=128,N=256
__device__ uint2 g_B2h[16 * 8 * 32];     // stage2  K=256,N=64 (sign-folded)
__device__ uint2 g_B3h[8 * 48 * 32];     // GRU Whh K=128,N=384
__device__ uint2 g_B4h[4 * 48 * 32];     // GRU Wih K=64, N=384
__device__ float g_xc[256];
__device__ float g_b2d[64];
__device__ float g_brz[256];
__device__ float g_bni[128];
__device__ float g_bnh[128];
__device__ float g_wt[384];
__device__ float g_blk_t[NBLK];
__device__ float g_blk_e[NBLK];
__device__ float g_blk_wout[NBLK * 64];
__device__ float g_blk_h[NBLK * 128];
__device__ float g_fs[8 * 128];          // raw faction sums (kC1 -> kC2)
__device__ float g_woutp[16 * 64];       // wout chunk partials (kC1 -> kC2)
__device__ float g_fm[8 * 128];
__device__ float g_go[128];

// ---------------- helpers ----------------
__device__ __forceinline__ unsigned packh2(float lo, float hi) {
    __half2 h = __floats2half2_rn(lo, hi);
    return *(unsigned*)&h;
}
__device__ __forceinline__ void mma16(float* c,
    unsigned a0, unsigned a1, unsigned a2, unsigned a3,
    unsigned b0, unsigned b1)
{
    asm volatile(
        "mma.sync.aligned.m16n8k16.row.col.f32.f16.f16.f32 "
        "{%0,%1,%2,%3},{%4,%5,%6,%7},{%8,%9},{%0,%1,%2,%3};"
        : "+f"(c[0]), "+f"(c[1]), "+f"(c[2]), "+f"(c[3])
        : "r"(a0), "r"(a1), "r"(a2), "r"(a3), "r"(b0), "r"(b1));
}
__device__ __forceinline__ void ldsm4(unsigned& a0, unsigned& a1, unsigned& a2, unsigned& a3,
                                      unsigned addr)
{
    asm volatile("ldmatrix.sync.aligned.m8n8.x4.shared.b16 {%0,%1,%2,%3}, [%4];"
                 : "=r"(a0), "=r"(a1), "=r"(a2), "=r"(a3) : "r"(addr));
}
__device__ __forceinline__ float sigmoid_f(float x) {
    return 1.f / (1.f + __expf(-x));
}

// ---------------- kA: merged weight pack + misc vectors ----------------
// flat tasks: [0,8192) B1h | [8192,12288) B2h | [12288,24576) B3h | [24576,30720) B4h
//             [30720,30976) xc | [30976,31040) b2d | [31040,31424) wt
//             [31424,31680) brz | [31680,31808) bni | [31808,31936) bnh
__global__ __launch_bounds__(512) void kA(
    const float* __restrict__ x,
    const float* __restrict__ W1a, const float* __restrict__ b1a,
    const float* __restrict__ W1g, const float* __restrict__ b1g,
    const float* __restrict__ b2a, const float* __restrict__ b2g,
    const float* __restrict__ W2a, const float* __restrict__ W2g,
    const float* __restrict__ Wih, const float* __restrict__ Whh,
    const float* __restrict__ bih, const float* __restrict__ bhh)
{
    int id = blockIdx.x * 512 + threadIdx.x;
    if (id < 8192) {                                  // B1h: B[k][u]=W1[u][64+k]
        int grp = id >> 10, rem = id & 1023;
        int nt = rem >> 5, lane = rem & 31;
        int t = lane & 3, g = lane >> 2;
        int u = nt * 8 + g;
        const float* wr = ((u < 128) ? (W1a + u * 192) : (W1g + (u - 128) * 192)) + 64 + grp * 16;
        g_B1h[id] = make_uint2(packh2(wr[2*t], wr[2*t+1]), packh2(wr[2*t+8], wr[2*t+9]));
    } else if (id < 12288) {                          // B2h: +W2a / -W2g
        int i = id - 8192;
        int grpG = i >> 8, rem = i & 255;
        int nt = rem >> 5, lane = rem & 31;
        int t = lane & 3, g = lane >> 2;
        int o = nt * 8 + g;
        if (grpG < 8) {
            const float* wr = W2a + o * 128 + grpG * 16;
            g_B2h[i] = make_uint2(packh2(wr[2*t], wr[2*t+1]), packh2(wr[2*t+8], wr[2*t+9]));
        } else {
            const float* wr = W2g + o * 128 + (grpG - 8) * 16;
            g_B2h[i] = make_uint2(packh2(-wr[2*t], -wr[2*t+1]), packh2(-wr[2*t+8], -wr[2*t+9]));
        }
    } else if (id < 24576) {                          // B3h: Whh[j][k]
        int i = id - 12288;
        int grp = i / 1536, rem = i % 1536;
        int nt = rem >> 5, lane = rem & 31;
        int t = lane & 3, g = lane >> 2;
        int j = nt * 8 + g;
        const float* wr = Whh + j * 128 + grp * 16;
        g_B3h[i] = make_uint2(packh2(wr[2*t], wr[2*t+1]), packh2(wr[2*t+8], wr[2*t+9]));
    } else if (id < 30720) {                          // B4h: Wih[j][k], k<64
        int i = id - 24576;
        int grp = i / 1536, rem = i % 1536;
        int nt = rem >> 5, lane = rem & 31;
        int t = lane & 3, g = lane >> 2;
        int j = nt * 8 + g;
        const float* wr = Wih + j * 65 + grp * 16;
        g_B4h[i] = make_uint2(packh2(wr[2*t], wr[2*t+1]), packh2(wr[2*t+8], wr[2*t+9]));
    } else if (id < 30976) {                          // xc (exact fp32 x-fold)
        int u = id - 30720;
        const float* W = (u < 128) ? W1a : W1g;
        const float* b = (u < 128) ? b1a : b1g;
        int j = u & 127;
        float s = b[j];
        const float* row = W + j * 192;
        #pragma unroll 8
        for (int k = 0; k < 64; k++) s += row[k] * x[k];
        g_xc[u] = s;
    } else if (id < 31040) {
        int o = id - 30976;
        g_b2d[o] = b2a[o] - b2g[o];
    } else if (id < 31424) {
        int j = id - 31040;
        g_wt[j] = Wih[j * 65 + 64];
    } else if (id < 31680) {
        int j = id - 31424;
        g_brz[j] = bih[j] + bhh[j];
    } else if (id < 31808) {
        int j = id - 31680;
        g_bni[j] = bih[256 + j];
    } else if (id < 31936) {
        int j = id - 31808;
        g_bnh[j] = bhh[256 + j];
    }
}

// ---------------- Kernel B: fused pipeline, 256thr/64cells, 3 blocks/SM (R12 layout) ----------------
__global__ __launch_bounds__(TPB, 3) void kB(
    const float* __restrict__ hiddens,
    float* __restrict__ dout)
{
    extern __shared__ float sm[];
    __half* h_h   = (__half*)(sm + OFF_HH);
    __half* c1h   = (__half*)(sm + OFF_C1H);
    float*  nh_s  = sm + OFF_C1H;        // aliases c1h after stage 2
    __half* outh  = (__half*)(sm + OFF_OUTH);
    float*  t_s   = sm + OFF_T;
    float*  e_s   = sm + OFF_E;
    float*  xc_s  = sm + OFF_XC;
    float*  b2d_s = sm + OFF_B2D;
    float*  brz_s = sm + OFF_BRZ;
    float*  bni_s = sm + OFF_BNI;
    float*  bnh_s = sm + OFF_BNH;
    float*  wt_s  = sm + OFF_WT;

    const int tid  = threadIdx.x;
    const int blk  = blockIdx.x;
    const int w    = tid >> 5;            // 0..7
    const int lane = tid & 31;
    const int t4   = lane & 3;
    const int g    = lane >> 2;

    // ldmatrix per-lane byte offsets (row = lane&15, col-half = lane>>4)
    const unsigned sb   = (unsigned)__cvta_generic_to_shared(sm);
    const int lrow = lane & 15, lcol = lane >> 4;
    const unsigned hB   = sb + OFF_HH  * 4 + 2u * (lrow * HHP  + lcol * 8);
    const unsigned c1B  = sb + OFF_C1H * 4 + 2u * (lrow * C1HP + lcol * 8);
    const unsigned oB   = sb + OFF_OUTH* 4 + 2u * (lrow * OHP  + lcol * 8);

    const float* Hg = hiddens + (size_t)blk * MT * 128;

    // ---- stage 0: load h tile (fp16) + constant tables ----
    #pragma unroll
    for (int i = tid; i < MT * 32; i += TPB) {       // 2048 float4
        float4 v = ((const float4*)Hg)[i];
        int c = i >> 5, k = (i & 31) << 2;
        unsigned* q = (unsigned*)(h_h + c * HHP + k);
        q[0] = packh2(v.x, v.y);
        q[1] = packh2(v.z, v.w);
    }
    { xc_s[tid] = g_xc[tid]; brz_s[tid] = g_brz[tid]; }
    if (tid < 64)  { b2d_s[tid] = g_b2d[tid]; }
    if (tid < 128) { bni_s[tid] = g_bni[tid]; bnh_s[tid] = g_bnh[tid]; }
    { if (tid < 128) wt_s[tid + 256] = g_wt[tid + 256]; wt_s[tid] = g_wt[tid]; }
    __syncthreads();

    // ---- stage 1: C1[64x256] = relu(h @ B1 + xc); two n-half passes (32 acc live) ----
    #pragma unroll 1
    for (int nh2 = 0; nh2 < 2; nh2++) {
        float acc[4][2][4];                          // [mt][n][c]
        #pragma unroll
        for (int m = 0; m < 4; m++)
            #pragma unroll
            for (int n = 0; n < 2; n++)
                #pragma unroll
                for (int c = 0; c < 4; c++) acc[m][n][c] = 0.f;
        #pragma unroll
        for (int grp = 0; grp < 8; grp++) {
            uint2 bv0 = g_B1h[(grp * 32 + 4 * w + 2 * nh2)     * 32 + lane];
            uint2 bv1 = g_B1h[(grp * 32 + 4 * w + 2 * nh2 + 1) * 32 + lane];
            #pragma unroll
            for (int m = 0; m < 4; m++) {
                unsigned a0, a1, a2, a3;
                ldsm4(a0, a1, a2, a3, hB + 2u * (m * 16 * HHP + grp * 16));
                mma16(acc[m][0], a0, a1, a2, a3, bv0.x, bv0.y);
                mma16(acc[m][1], a0, a1, a2, a3, bv1.x, bv1.y);
            }
        }
        #pragma unroll
        for (int m = 0; m < 4; m++) {
            int r0 = m * 16 + g, r1 = r0 + 8;
            #pragma unroll
            for (int n = 0; n < 2; n++) {
                int cb = (4 * w + 2 * nh2 + n) * 8 + 2 * t4;
                float x0 = xc_s[cb], x1 = xc_s[cb + 1];
                *(unsigned*)(c1h + r0 * C1HP + cb) =
                    packh2(fmaxf(acc[m][n][0] + x0, 0.f), fmaxf(acc[m][n][1] + x1, 0.f));
                *(unsigned*)(c1h + r1 * C1HP + cb) =
                    packh2(fmaxf(acc[m][n][2] + x0, 0.f), fmaxf(acc[m][n][3] + x1, 0.f));
            }
        }
    }
    __syncthreads();

    // ---- stage 2: out[64x64] = C1 @ B2 + b2d; warp = (mt = w&3, ng = w>>2), full K=256 ----
    {
        const int mt = w & 3, ng = w >> 2;
        float acc[4][4];
        #pragma unroll
        for (int n = 0; n < 4; n++)
            #pragma unroll
            for (int c = 0; c < 4; c++) acc[n][c] = 0.f;
        #pragma unroll
        for (int grpG = 0; grpG < 16; grpG++) {
            unsigned a0, a1, a2, a3;
            ldsm4(a0, a1, a2, a3, c1B + 2u * (mt * 16 * C1HP + grpG * 16));
            #pragma unroll
            for (int ni = 0; ni < 4; ni++) {
                uint2 bv = g_B2h[(grpG * 8 + ng * 4 + ni) * 32 + lane];
                mma16(acc[ni], a0, a1, a2, a3, bv.x, bv.y);
            }
        }
        int r0 = mt * 16 + g, r1 = r0 + 8;
        #pragma unroll
        for (int ni = 0; ni < 4; ni++) {
            int o = (ng * 4 + ni) * 8 + 2 * t4;
            float x0 = b2d_s[o], x1 = b2d_s[o + 1];
            *(unsigned*)(outh + r0 * OHP + o) = packh2(acc[ni][0] + x0, acc[ni][1] + x1);
            *(unsigned*)(outh + r1 * OHP + o) = packh2(acc[ni][2] + x0, acc[ni][3] + x1);
        }
    }
    __syncthreads();

    // ---- t/e (tid<64) — overlapped with GRU pass-0 mma of all warps ----
    if (tid < 64) {
        const unsigned* orow = (const unsigned*)(outh + tid * OHP);
        float s = 0.f;
        #pragma unroll
        for (int c = 0; c < 32; c++) {
            float2 f = __half22float2(*(const __half2*)(orow + c));
            s += f.x * f.x + f.y * f.y;
        }
        float tt = s * (1.f / 64.f);
        t_s[tid] = tt;
        e_s[tid] = expf(tt);
    }

    // ---- GRU: 4 passes (m-half mh, j-tile jt); warp's j-slice = [16w+8jt, 16w+8jt+8) ----
    #pragma unroll 1
    for (int p = 0; p < 4; p++) {
        const int mh = p >> 1, jt = p & 1;
        float aR[2][4], aZ[2][4], aNh[2][4], aNi[2][4];   // [mi][c]  (32 acc live)
        #pragma unroll
        for (int m = 0; m < 2; m++)
            #pragma unroll
            for (int c = 0; c < 4; c++)
                { aR[m][c] = 0.f; aZ[m][c] = 0.f; aNh[m][c] = 0.f; aNi[m][c] = 0.f; }

        // h-side (K=128)
        #pragma unroll
        for (int grp = 0; grp < 8; grp++) {
            uint2 bR = g_B3h[(grp * 48 + 2 * w + jt)      * 32 + lane];
            uint2 bZ = g_B3h[(grp * 48 + 16 + 2 * w + jt) * 32 + lane];
            uint2 bN = g_B3h[(grp * 48 + 32 + 2 * w + jt) * 32 + lane];
            #pragma unroll
            for (int mi = 0; mi < 2; mi++) {
                unsigned a0, a1, a2, a3;
                ldsm4(a0, a1, a2, a3, hB + 2u * ((mh * 2 + mi) * 16 * HHP + grp * 16));
                mma16(aR[mi],  a0, a1, a2, a3, bR.x, bR.y);
                mma16(aZ[mi],  a0, a1, a2, a3, bZ.x, bZ.y);
                mma16(aNh[mi], a0, a1, a2, a3, bN.x, bN.y);
            }
        }
        // i-side (K=64): r,z accumulate on; n separate
        #pragma unroll
        for (int grp = 0; grp < 4; grp++) {
            uint2 bR = g_B4h[(grp * 48 + 2 * w + jt)      * 32 + lane];
            uint2 bZ = g_B4h[(grp * 48 + 16 + 2 * w + jt) * 32 + lane];
            uint2 bN = g_B4h[(grp * 48 + 32 + 2 * w + jt) * 32 + lane];
            #pragma unroll
            for (int mi = 0; mi < 2; mi++) {
                unsigned a0, a1, a2, a3;
                ldsm4(a0, a1, a2, a3, oB + 2u * ((mh * 2 + mi) * 16 * OHP + grp * 16));
                mma16(aR[mi],  a0, a1, a2, a3, bR.x, bR.y);
                mma16(aZ[mi],  a0, a1, a2, a3, bZ.x, bZ.y);
                mma16(aNi[mi], a0, a1, a2, a3, bN.x, bN.y);
            }
        }

        if (p == 0) __syncthreads();   // t_s/e_s ready; stage-2 c1h reads complete -> nh alias safe

        // epilogue: nh into staging (c1h alias); exact fp32 h re-read from global (L2-hot)
        {
            int j0 = 16 * w + jt * 8 + 2 * t4;
            float brzr0 = brz_s[j0],       brzr1 = brz_s[j0 + 1];
            float brzz0 = brz_s[128 + j0], brzz1 = brz_s[128 + j0 + 1];
            float bni0  = bni_s[j0],       bni1  = bni_s[j0 + 1];
            float bnh0  = bnh_s[j0],       bnh1  = bnh_s[j0 + 1];
            float wtr0 = wt_s[j0],        wtr1 = wt_s[j0 + 1];
            float wtz0 = wt_s[128 + j0],  wtz1 = wt_s[128 + j0 + 1];
            float wtn0 = wt_s[256 + j0],  wtn1 = wt_s[256 + j0 + 1];
            #pragma unroll
            for (int mi = 0; mi < 2; mi++) {
                int r0 = (mh * 2 + mi) * 16 + g, r1 = r0 + 8;
                float tv0 = t_s[r0], tv1 = t_s[r1];
                float2 hv0 = *(const float2*)(Hg + r0 * 128 + j0);
                float2 hv1 = *(const float2*)(Hg + r1 * 128 + j0);
                {
                    float r = sigmoid_f(aR[mi][0] + brzr0 + tv0 * wtr0);
                    float z = sigmoid_f(aZ[mi][0] + brzz0 + tv0 * wtz0);
                    float n = tanhf(aNi[mi][0] + tv0 * wtn0 + bni0 + r * (aNh[mi][0] + bnh0));
                    nh_s[r0 * NHP + j0] = (1.f - z) * n + z * hv0.x;
                }
                {
                    float r = sigmoid_f(aR[mi][1] + brzr1 + tv0 * wtr1);
                    float z = sigmoid_f(aZ[mi][1] + brzz1 + tv0 * wtz1);
                    float n = tanhf(aNi[mi][1] + tv0 * wtn1 + bni1 + r * (aNh[mi][1] + bnh1));
                    nh_s[r0 * NHP + j0 + 1] = (1.f - z) * n + z * hv0.y;
                }
                {
                    float r = sigmoid_f(aR[mi][2] + brzr0 + tv1 * wtr0);
                    float z = sigmoid_f(aZ[mi][2] + brzz0 + tv1 * wtz0);
                    float n = tanhf(aNi[mi][2] + tv1 * wtn0 + bni0 + r * (aNh[mi][2] + bnh0));
                    nh_s[r1 * NHP + j0] = (1.f - z) * n + z * hv1.x;
                }
                {
                    float r = sigmoid_f(aR[mi][3] + brzr1 + tv1 * wtr1);
                    float z = sigmoid_f(aZ[mi][3] + brzz1 + tv1 * wtz1);
                    float n = tanhf(aNi[mi][3] + tv1 * wtn1 + bni1 + r * (aNh[mi][3] + bnh1));
                    nh_s[r1 * NHP + j0 + 1] = (1.f - z) * n + z * hv1.y;
                }
            }
        }
    }
    __syncthreads();

    // ---- store new_h (pre-sync) coalesced; block partials ----
    float* NH = dout + 65 + (size_t)blk * MT * 128;
    #pragma unroll
    for (int i = tid; i < MT * 128; i += TPB) {
        int c = i >> 7, k = i & 127;
        NH[i] = nh_s[c * NHP + k];
    }
    if (tid < 128) {
        float s = 0.f;
        #pragma unroll 8
        for (int c = 0; c < MT; c++) s += nh_s[c * NHP + tid];
        g_blk_h[(size_t)blk * 128 + tid] = s;
    }
    if (tid < 64) {
        float s = 0.f;
        #pragma unroll 8
        for (int c = 0; c < MT; c++) s += e_s[c] * __half2float(outh[c * OHP + tid]);
        g_blk_wout[(size_t)blk * 64 + tid] = s;
    } else if (tid == 64) {
        float s = 0.f;
        for (int c = 0; c < MT; c++) s += t_s[c];
        g_blk_t[blk] = s;
    } else if (tid == 96) {
        float s = 0.f;
        for (int c = 0; c < MT; c++) s += e_s[c];
        g_blk_e[blk] = s;
    }
}

// ---------------- kC1: parallel partial reductions (24 blocks) ----------------
__global__ __launch_bounds__(128) void kC1(void)
{
    const int b = blockIdx.x;
    const int tid = threadIdx.x;
    if (b < 8) {
        // faction sums: faction b, hidden j=tid; 256 kB-blocks per faction
        const float* p = g_blk_h + (size_t)(b * 256) * 128 + tid;
        float s = 0.f;
        #pragma unroll 8
        for (int k = 0; k < 256; k++) s += p[k * 128];
        g_fs[b * 128 + tid] = s;
        g_fm[b * 128 + tid] = s * (1.f / 16384.f);
    } else if (tid < 64) {
        // wout chunk (b-8): 128 kB-blocks x 64 outputs
        int ch = b - 8;
        const float* p = g_blk_wout + (size_t)(ch * 128) * 64 + tid;
        float s = 0.f;
        #pragma unroll 8
        for (int k = 0; k < 128; k++) s += p[k * 64];
        g_woutp[ch * 64 + tid] = s;
    }
}

// ---------------- kC2: combine partials + head (1 block) ----------------
__global__ __launch_bounds__(1024) void kC2(
    const float* __restrict__ Wo, const float* __restrict__ bo,
    float* __restrict__ dout)
{
    __shared__ float s_red[1024];
    __shared__ float s_red2[1024];
    __shared__ float s_comb[64];
    __shared__ float s_esum;
    const int tid = threadIdx.x;

    if (tid < 128) {
        float gg = 0.f;
        #pragma unroll
        for (int f = 0; f < 8; f++) gg += g_fs[f * 128 + tid];
        g_go[tid] = gg * (1.f / (float)NCELLS);
    }
    if (tid < 64) {
        float s = 0.f;
        #pragma unroll
        for (int ch = 0; ch < 16; ch++) s += g_woutp[ch * 64 + tid];
        s_comb[tid] = s;
    }

    // exp-sum + t-sum (2 elements per thread, NBLK==2048)
    float se = 0.f, st = 0.f;
    #pragma unroll
    for (int i = tid; i < NBLK; i += 1024) { se += g_blk_e[i]; st += g_blk_t[i]; }
    s_red[tid]  = se;
    s_red2[tid] = st;
    __syncthreads();
    for (int off = 512; off > 0; off >>= 1) {
        if (tid < off) { s_red[tid] += s_red[tid + off]; s_red2[tid] += s_red2[tid + off]; }
        __syncthreads();
    }
    if (tid == 0) {
        s_esum = s_red[0];
        dout[64] = s_red2[0] * (1.f / (float)NCELLS);
    }
    __syncthreads();

    if (tid < 64) s_comb[tid] *= (1.f / s_esum);
    __syncthreads();
    if (tid < 64) {
        float p = bo[tid];
        const float* wr = Wo + tid * 64;
        #pragma unroll 8
        for (int o = 0; o < 64; o++) p += wr[o] * s_comb[o];
        dout[tid] = p;
    }
}

// ---------------- Kernel D: faction sync, float4 RMW, grid 4096 (2 f4/thread) ----------------
// nh = dout+65; nh+3 is 16B-aligned. Chunks cover e in [3, 16777215); peel e=0,1,2 and e=16777215.
__global__ __launch_bounds__(512) void kD(float* __restrict__ nh, const void* __restrict__ stepPtr)
{
    int iv = *(const int*)stepPtr;
    int step = (iv >= 0 && iv < 1000000) ? iv : (int)(*(const float*)stepPtr);
    const bool debate = (step > 5);

    if (blockIdx.x == 0 && threadIdx.x < 4) {
        unsigned e = (threadIdx.x < 3) ? threadIdx.x : 16777215u;
        unsigned cell = e >> 7, j = e & 127u;
        unsigned f = cell >> 14, pos = cell & 16383u;
        float v = nh[e];
        v = 0.85f * v + 0.15f * g_fm[f * 128 + j];
        if (debate && pos < 4096u) v = 0.85f * v + 0.15f * g_go[j];
        nh[e] = v;
    }

    float4* nh4 = (float4*)(nh + 3);
    unsigned base = blockIdx.x * 512u + threadIdx.x;
    const unsigned stride = 4096u * 512u;
    #pragma unroll
    for (int r = 0; r < 2; r++) {
        unsigned q = base + (unsigned)r * stride;
        if (q < 4194303u) {
            float4 v = nh4[q];
            float va[4] = {v.x, v.y, v.z, v.w};
            unsigned e0 = 3u + 4u * q;
            #pragma unroll
            for (int i = 0; i < 4; i++) {
                unsigned e = e0 + (unsigned)i;
                unsigned cell = e >> 7, j = e & 127u;
                unsigned f = cell >> 14, pos = cell & 16383u;
                float val = va[i];
                val = 0.85f * val + 0.15f * g_fm[f * 128 + j];
                if (debate && pos < 4096u) val = 0.85f * val + 0.15f * g_go[j];
                va[i] = val;
            }
            nh4[q] = make_float4(va[0], va[1], va[2], va[3]);
        }
    }
}

// ---------------- launcher ----------------
extern "C" void kernel_launch(void* const* d_in, const int* in_sizes, int n_in,
                              void* d_out, int out_size)
{
    const float* x    = (const float*)d_in[0];
    const float* hid  = (const float*)d_in[1];
    const float* W1a  = (const float*)d_in[2];
    const float* b1a  = (const float*)d_in[3];
    const float* W2a  = (const float*)d_in[4];
    const float* b2a  = (const float*)d_in[5];
    const float* W1g  = (const float*)d_in[6];
    const float* b1g  = (const float*)d_in[7];
    const float* W2g  = (const float*)d_in[8];
    const float* b2g  = (const float*)d_in[9];
    const float* Wih  = (const float*)d_in[10];
    const float* Whh  = (const float*)d_in[11];
    const float* bih  = (const float*)d_in[12];
    const float* bhh  = (const float*)d_in[13];
    const float* Wo   = (const float*)d_in[14];
    const float* bo   = (const float*)d_in[15];
    const void*  step = (n_in > 16) ? (const void*)d_in[16] : (const void*)d_in[15];

    float* out = (float*)d_out;
    float* nh  = out + 65;

    cudaFuncSetAttribute(kB, cudaFuncAttributeMaxDynamicSharedMemorySize, SMEM_KB_BYTES);

    kA<<<63, 512>>>(x, W1a, b1a, W1g, b1g, b2a, b2g, W2a, W2g, Wih, Whh, bih, bhh);
    kB<<<NBLK, TPB, SMEM_KB_BYTES>>>(hid, out);
    kC1<<<24, 128>>>();
    kC2<<<1, 1024>>>(Wo, bo, out);
    kD<<<4096, 512>>>(nh, step);
}

// round 16
// speedup vs baseline: 1.1134x; 1.0310x over previous
#include <cuda_runtime.h>
#include <cuda_fp16.h>
#include <stdint.h>
#include <math.h>

// ---------------- problem constants ----------------
#define NCELLS 131072
#define MT   64
#define TPB  256
#define NBLK (NCELLS / MT)   // 2048

// ---------------- smem layout (float offsets) ----------------
// all half pitches are ≡ 16 (mod 128) BYTES -> ldmatrix 8-row groups conflict-free
#define HHP   136            // h_h half pitch   (272 B)
#define C1HP  264            // C1h half pitch   (528 B)
#define OHP   72             // out_h half pitch (144 B)
#define NHP   132            // nh fp32 pitch (aliases C1 region exactly: 64*132 = 64*264/2)

#define OFF_HH   0                        // 64*136 h = 4352 floats
#define OFF_C1H  4352                     // 64*264 h = 8448 floats (nh fp32 alias 64*132)
#define OFF_OUTH 12800                    // 64*72 h  = 2304 floats
#define OFF_T    15104                    // 64
#define OFF_E    15168                    // 64
#define OFF_XC   15232                    // 256
#define OFF_B2D  15488                    // 64
#define OFF_BRZ  15552                    // 256
#define OFF_BNI  15808                    // 128
#define OFF_BNH  15936                    // 128
#define OFF_WT   16064                    // 384
#define SMEM_KB_FLOATS 16448
#define SMEM_KB_BYTES  (SMEM_KB_FLOATS * 4)   // 65792 B -> 3 blocks/SM

// ---------------- device scratch (static, allocation-free) ----------------
__device__ uint2 g_B1h[8 * 32 * 32];     // stage1  K=128,N=256
__device__ uint2 g_B2h[16 * 8 * 32];     // stage2  K=256,N=64 (sign-folded)
__device__ uint2 g_B3h[8 * 48 * 32];     // GRU Whh K=128,N=384
__device__ uint2 g_B4h[4 * 48 * 32];     // GRU Wih K=64, N=384
__device__ float g_xc[256];
__device__ float g_b2d[64];
__device__ float g_brz[256];
__device__ float g_bni[128];
__device__ float g_bnh[128];
__device__ float g_wt[384];
__device__ float g_blk_t[NBLK];
__device__ float g_blk_e[NBLK];
__device__ float g_blk_wout[NBLK * 64];
__device__ float g_blk_h[NBLK * 128];
__device__ float g_fs[8 * 128];          // raw faction sums
__device__ float g_woutp[16 * 64];       // wout chunk partials
__device__ float g_fm[8 * 128];
__device__ float g_go[128];
__device__ float g_esum_v;               // softmax denominator
__device__ int   g_ctr;                  // completion ticket (reset by combiner)

// ---------------- helpers ----------------
__device__ __forceinline__ unsigned packh2(float lo, float hi) {
    __half2 h = __floats2half2_rn(lo, hi);
    return *(unsigned*)&h;
}
__device__ __forceinline__ void mma16(float* c,
    unsigned a0, unsigned a1, unsigned a2, unsigned a3,
    unsigned b0, unsigned b1)
{
    asm volatile(
        "mma.sync.aligned.m16n8k16.row.col.f32.f16.f16.f32 "
        "{%0,%1,%2,%3},{%4,%5,%6,%7},{%8,%9},{%0,%1,%2,%3};"
        : "+f"(c[0]), "+f"(c[1]), "+f"(c[2]), "+f"(c[3])
        : "r"(a0), "r"(a1), "r"(a2), "r"(a3), "r"(b0), "r"(b1));
}
__device__ __forceinline__ void ldsm4(unsigned& a0, unsigned& a1, unsigned& a2, unsigned& a3,
                                      unsigned addr)
{
    asm volatile("ldmatrix.sync.aligned.m8n8.x4.shared.b16 {%0,%1,%2,%3}, [%4];"
                 : "=r"(a0), "=r"(a1), "=r"(a2), "=r"(a3) : "r"(addr));
}
__device__ __forceinline__ float sigmoid_f(float x) {
    return 1.f / (1.f + __expf(-x));
}

// ---------------- kA: merged weight pack + misc vectors ----------------
__global__ __launch_bounds__(512) void kA(
    const float* __restrict__ x,
    const float* __restrict__ W1a, const float* __restrict__ b1a,
    const float* __restrict__ W1g, const float* __restrict__ b1g,
    const float* __restrict__ b2a, const float* __restrict__ b2g,
    const float* __restrict__ W2a, const float* __restrict__ W2g,
    const float* __restrict__ Wih, const float* __restrict__ Whh,
    const float* __restrict__ bih, const float* __restrict__ bhh)
{
    int id = blockIdx.x * 512 + threadIdx.x;
    if (id < 8192) {                                  // B1h: B[k][u]=W1[u][64+k]
        int grp = id >> 10, rem = id & 1023;
        int nt = rem >> 5, lane = rem & 31;
        int t = lane & 3, g = lane >> 2;
        int u = nt * 8 + g;
        const float* wr = ((u < 128) ? (W1a + u * 192) : (W1g + (u - 128) * 192)) + 64 + grp * 16;
        g_B1h[id] = make_uint2(packh2(wr[2*t], wr[2*t+1]), packh2(wr[2*t+8], wr[2*t+9]));
    } else if (id < 12288) {                          // B2h: +W2a / -W2g
        int i = id - 8192;
        int grpG = i >> 8, rem = i & 255;
        int nt = rem >> 5, lane = rem & 31;
        int t = lane & 3, g = lane >> 2;
        int o = nt * 8 + g;
        if (grpG < 8) {
            const float* wr = W2a + o * 128 + grpG * 16;
            g_B2h[i] = make_uint2(packh2(wr[2*t], wr[2*t+1]), packh2(wr[2*t+8], wr[2*t+9]));
        } else {
            const float* wr = W2g + o * 128 + (grpG - 8) * 16;
            g_B2h[i] = make_uint2(packh2(-wr[2*t], -wr[2*t+1]), packh2(-wr[2*t+8], -wr[2*t+9]));
        }
    } else if (id < 24576) {                          // B3h: Whh[j][k]
        int i = id - 12288;
        int grp = i / 1536, rem = i % 1536;
        int nt = rem >> 5, lane = rem & 31;
        int t = lane & 3, g = lane >> 2;
        int j = nt * 8 + g;
        const float* wr = Whh + j * 128 + grp * 16;
        g_B3h[i] = make_uint2(packh2(wr[2*t], wr[2*t+1]), packh2(wr[2*t+8], wr[2*t+9]));
    } else if (id < 30720) {                          // B4h: Wih[j][k], k<64
        int i = id - 24576;
        int grp = i / 1536, rem = i % 1536;
        int nt = rem >> 5, lane = rem & 31;
        int t = lane & 3, g = lane >> 2;
        int j = nt * 8 + g;
        const float* wr = Wih + j * 65 + grp * 16;
        g_B4h[i] = make_uint2(packh2(wr[2*t], wr[2*t+1]), packh2(wr[2*t+8], wr[2*t+9]));
    } else if (id < 30976) {                          // xc (exact fp32 x-fold)
        int u = id - 30720;
        const float* W = (u < 128) ? W1a : W1g;
        const float* b = (u < 128) ? b1a : b1g;
        int j = u & 127;
        float s = b[j];
        const float* row = W + j * 192;
        #pragma unroll 8
        for (int k = 0; k < 64; k++) s += row[k] * x[k];
        g_xc[u] = s;
    } else if (id < 31040) {
        int o = id - 30976;
        g_b2d[o] = b2a[o] - b2g[o];
    } else if (id < 31424) {
        int j = id - 31040;
        g_wt[j] = Wih[j * 65 + 64];
    } else if (id < 31680) {
        int j = id - 31424;
        g_brz[j] = bih[j] + bhh[j];
    } else if (id < 31808) {
        int j = id - 31680;
        g_bni[j] = bih[256 + j];
    } else if (id < 31936) {
        int j = id - 31808;
        g_bnh[j] = bhh[256 + j];
    }
}

// ---------------- Kernel B: fused pipeline, 256thr/64cells, 3 blocks/SM (R12 layout) ----------------
__global__ __launch_bounds__(TPB, 3) void kB(
    const float* __restrict__ hiddens,
    float* __restrict__ dout)
{
    extern __shared__ float sm[];
    __half* h_h   = (__half*)(sm + OFF_HH);
    __half* c1h   = (__half*)(sm + OFF_C1H);
    float*  nh_s  = sm + OFF_C1H;        // aliases c1h after stage 2
    __half* outh  = (__half*)(sm + OFF_OUTH);
    float*  t_s   = sm + OFF_T;
    float*  e_s   = sm + OFF_E;
    float*  xc_s  = sm + OFF_XC;
    float*  b2d_s = sm + OFF_B2D;
    float*  brz_s = sm + OFF_BRZ;
    float*  bni_s = sm + OFF_BNI;
    float*  bnh_s = sm + OFF_BNH;
    float*  wt_s  = sm + OFF_WT;

    const int tid  = threadIdx.x;
    const int blk  = blockIdx.x;
    const int w    = tid >> 5;            // 0..7
    const int lane = tid & 31;
    const int t4   = lane & 3;
    const int g    = lane >> 2;

    const unsigned sb   = (unsigned)__cvta_generic_to_shared(sm);
    const int lrow = lane & 15, lcol = lane >> 4;
    const unsigned hB   = sb + OFF_HH  * 4 + 2u * (lrow * HHP  + lcol * 8);
    const unsigned c1B  = sb + OFF_C1H * 4 + 2u * (lrow * C1HP + lcol * 8);
    const unsigned oB   = sb + OFF_OUTH* 4 + 2u * (lrow * OHP  + lcol * 8);

    const float* Hg = hiddens + (size_t)blk * MT * 128;

    // ---- stage 0: load h tile (fp16) + constant tables ----
    #pragma unroll
    for (int i = tid; i < MT * 32; i += TPB) {       // 2048 float4
        float4 v = ((const float4*)Hg)[i];
        int c = i >> 5, k = (i & 31) << 2;
        unsigned* q = (unsigned*)(h_h + c * HHP + k);
        q[0] = packh2(v.x, v.y);
        q[1] = packh2(v.z, v.w);
    }
    { xc_s[tid] = g_xc[tid]; brz_s[tid] = g_brz[tid]; }
    if (tid < 64)  { b2d_s[tid] = g_b2d[tid]; }
    if (tid < 128) { bni_s[tid] = g_bni[tid]; bnh_s[tid] = g_bnh[tid]; }
    { if (tid < 128) wt_s[tid + 256] = g_wt[tid + 256]; wt_s[tid] = g_wt[tid]; }
    __syncthreads();

    // ---- stage 1: C1[64x256] = relu(h @ B1 + xc); two n-half passes (32 acc live) ----
    #pragma unroll 1
    for (int nh2 = 0; nh2 < 2; nh2++) {
        float acc[4][2][4];                          // [mt][n][c]
        #pragma unroll
        for (int m = 0; m < 4; m++)
            #pragma unroll
            for (int n = 0; n < 2; n++)
                #pragma unroll
                for (int c = 0; c < 4; c++) acc[m][n][c] = 0.f;
        #pragma unroll
        for (int grp = 0; grp < 8; grp++) {
            uint2 bv0 = g_B1h[(grp * 32 + 4 * w + 2 * nh2)     * 32 + lane];
            uint2 bv1 = g_B1h[(grp * 32 + 4 * w + 2 * nh2 + 1) * 32 + lane];
            #pragma unroll
            for (int m = 0; m < 4; m++) {
                unsigned a0, a1, a2, a3;
                ldsm4(a0, a1, a2, a3, hB + 2u * (m * 16 * HHP + grp * 16));
                mma16(acc[m][0], a0, a1, a2, a3, bv0.x, bv0.y);
                mma16(acc[m][1], a0, a1, a2, a3, bv1.x, bv1.y);
            }
        }
        #pragma unroll
        for (int m = 0; m < 4; m++) {
            int r0 = m * 16 + g, r1 = r0 + 8;
            #pragma unroll
            for (int n = 0; n < 2; n++) {
                int cb = (4 * w + 2 * nh2 + n) * 8 + 2 * t4;
                float x0 = xc_s[cb], x1 = xc_s[cb + 1];
                *(unsigned*)(c1h + r0 * C1HP + cb) =
                    packh2(fmaxf(acc[m][n][0] + x0, 0.f), fmaxf(acc[m][n][1] + x1, 0.f));
                *(unsigned*)(c1h + r1 * C1HP + cb) =
                    packh2(fmaxf(acc[m][n][2] + x0, 0.f), fmaxf(acc[m][n][3] + x1, 0.f));
            }
        }
    }
    __syncthreads();

    // ---- stage 2: out[64x64] = C1 @ B2 + b2d; warp = (mt = w&3, ng = w>>2), full K=256 ----
    {
        const int mt = w & 3, ng = w >> 2;
        float acc[4][4];
        #pragma unroll
        for (int n = 0; n < 4; n++)
            #pragma unroll
            for (int c = 0; c < 4; c++) acc[n][c] = 0.f;
        #pragma unroll
        for (int grpG = 0; grpG < 16; grpG++) {
            unsigned a0, a1, a2, a3;
            ldsm4(a0, a1, a2, a3, c1B + 2u * (mt * 16 * C1HP + grpG * 16));
            #pragma unroll
            for (int ni = 0; ni < 4; ni++) {
                uint2 bv = g_B2h[(grpG * 8 + ng * 4 + ni) * 32 + lane];
                mma16(acc[ni], a0, a1, a2, a3, bv.x, bv.y);
            }
        }
        int r0 = mt * 16 + g, r1 = r0 + 8;
        #pragma unroll
        for (int ni = 0; ni < 4; ni++) {
            int o = (ng * 4 + ni) * 8 + 2 * t4;
            float x0 = b2d_s[o], x1 = b2d_s[o + 1];
            *(unsigned*)(outh + r0 * OHP + o) = packh2(acc[ni][0] + x0, acc[ni][1] + x1);
            *(unsigned*)(outh + r1 * OHP + o) = packh2(acc[ni][2] + x0, acc[ni][3] + x1);
        }
    }
    __syncthreads();

    // ---- t/e (tid<64) — overlapped with GRU pass-0 mma of all warps ----
    if (tid < 64) {
        const unsigned* orow = (const unsigned*)(outh + tid * OHP);
        float s = 0.f;
        #pragma unroll
        for (int c = 0; c < 32; c++) {
            float2 f = __half22float2(*(const __half2*)(orow + c));
            s += f.x * f.x + f.y * f.y;
        }
        float tt = s * (1.f / 64.f);
        t_s[tid] = tt;
        e_s[tid] = expf(tt);
    }

    // ---- GRU: 4 passes (m-half mh, j-tile jt); warp's j-slice = [16w+8jt, 16w+8jt+8) ----
    #pragma unroll 1
    for (int p = 0; p < 4; p++) {
        const int mh = p >> 1, jt = p & 1;
        float aR[2][4], aZ[2][4], aNh[2][4], aNi[2][4];   // [mi][c]  (32 acc live)
        #pragma unroll
        for (int m = 0; m < 2; m++)
            #pragma unroll
            for (int c = 0; c < 4; c++)
                { aR[m][c] = 0.f; aZ[m][c] = 0.f; aNh[m][c] = 0.f; aNi[m][c] = 0.f; }

        // h-side (K=128)
        #pragma unroll
        for (int grp = 0; grp < 8; grp++) {
            uint2 bR = g_B3h[(grp * 48 + 2 * w + jt)      * 32 + lane];
            uint2 bZ = g_B3h[(grp * 48 + 16 + 2 * w + jt) * 32 + lane];
            uint2 bN = g_B3h[(grp * 48 + 32 + 2 * w + jt) * 32 + lane];
            #pragma unroll
            for (int mi = 0; mi < 2; mi++) {
                unsigned a0, a1, a2, a3;
                ldsm4(a0, a1, a2, a3, hB + 2u * ((mh * 2 + mi) * 16 * HHP + grp * 16));
                mma16(aR[mi],  a0, a1, a2, a3, bR.x, bR.y);
                mma16(aZ[mi],  a0, a1, a2, a3, bZ.x, bZ.y);
                mma16(aNh[mi], a0, a1, a2, a3, bN.x, bN.y);
            }
        }
        // i-side (K=64): r,z accumulate on; n separate
        #pragma unroll
        for (int grp = 0; grp < 4; grp++) {
            uint2 bR = g_B4h[(grp * 48 + 2 * w + jt)      * 32 + lane];
            uint2 bZ = g_B4h[(grp * 48 + 16 + 2 * w + jt) * 32 + lane];
            uint2 bN = g_B4h[(grp * 48 + 32 + 2 * w + jt) * 32 + lane];
            #pragma unroll
            for (int mi = 0; mi < 2; mi++) {
                unsigned a0, a1, a2, a3;
                ldsm4(a0, a1, a2, a3, oB + 2u * ((mh * 2 + mi) * 16 * OHP + grp * 16));
                mma16(aR[mi],  a0, a1, a2, a3, bR.x, bR.y);
                mma16(aZ[mi],  a0, a1, a2, a3, bZ.x, bZ.y);
                mma16(aNi[mi], a0, a1, a2, a3, bN.x, bN.y);
            }
        }

        if (p == 0) __syncthreads();   // t_s/e_s ready; stage-2 c1h reads complete -> nh alias safe

        // epilogue: nh into staging (c1h alias); exact fp32 h re-read from global (L2-hot)
        {
            int j0 = 16 * w + jt * 8 + 2 * t4;
            float brzr0 = brz_s[j0],       brzr1 = brz_s[j0 + 1];
            float brzz0 = brz_s[128 + j0], brzz1 = brz_s[128 + j0 + 1];
            float bni0  = bni_s[j0],       bni1  = bni_s[j0 + 1];
            float bnh0  = bnh_s[j0],       bnh1  = bnh_s[j0 + 1];
            float wtr0 = wt_s[j0],        wtr1 = wt_s[j0 + 1];
            float wtz0 = wt_s[128 + j0],  wtz1 = wt_s[128 + j0 + 1];
            float wtn0 = wt_s[256 + j0],  wtn1 = wt_s[256 + j0 + 1];
            #pragma unroll
            for (int mi = 0; mi < 2; mi++) {
                int r0 = (mh * 2 + mi) * 16 + g, r1 = r0 + 8;
                float tv0 = t_s[r0], tv1 = t_s[r1];
                float2 hv0 = *(const float2*)(Hg + r0 * 128 + j0);
                float2 hv1 = *(const float2*)(Hg + r1 * 128 + j0);
                {
                    float r = sigmoid_f(aR[mi][0] + brzr0 + tv0 * wtr0);
                    float z = sigmoid_f(aZ[mi][0] + brzz0 + tv0 * wtz0);
                    float n = tanhf(aNi[mi][0] + tv0 * wtn0 + bni0 + r * (aNh[mi][0] + bnh0));
                    nh_s[r0 * NHP + j0] = (1.f - z) * n + z * hv0.x;
                }
                {
                    float r = sigmoid_f(aR[mi][1] + brzr1 + tv0 * wtr1);
                    float z = sigmoid_f(aZ[mi][1] + brzz1 + tv0 * wtz1);
                    float n = tanhf(aNi[mi][1] + tv0 * wtn1 + bni1 + r * (aNh[mi][1] + bnh1));
                    nh_s[r0 * NHP + j0 + 1] = (1.f - z) * n + z * hv0.y;
                }
                {
                    float r = sigmoid_f(aR[mi][2] + brzr0 + tv1 * wtr0);
                    float z = sigmoid_f(aZ[mi][2] + brzz0 + tv1 * wtz0);
                    float n = tanhf(aNi[mi][2] + tv1 * wtn0 + bni0 + r * (aNh[mi][2] + bnh0));
                    nh_s[r1 * NHP + j0] = (1.f - z) * n + z * hv1.x;
                }
                {
                    float r = sigmoid_f(aR[mi][3] + brzr1 + tv1 * wtr1);
                    float z = sigmoid_f(aZ[mi][3] + brzz1 + tv1 * wtz1);
                    float n = tanhf(aNi[mi][3] + tv1 * wtn1 + bni1 + r * (aNh[mi][3] + bnh1));
                    nh_s[r1 * NHP + j0 + 1] = (1.f - z) * n + z * hv1.y;
                }
            }
        }
    }
    __syncthreads();

    // ---- store new_h (pre-sync) coalesced; block partials ----
    float* NH = dout + 65 + (size_t)blk * MT * 128;
    #pragma unroll
    for (int i = tid; i < MT * 128; i += TPB) {
        int c = i >> 7, k = i & 127;
        NH[i] = nh_s[c * NHP + k];
    }
    if (tid < 128) {
        float s = 0.f;
        #pragma unroll 8
        for (int c = 0; c < MT; c++) s += nh_s[c * NHP + tid];
        g_blk_h[(size_t)blk * 128 + tid] = s;
    }
    if (tid < 64) {
        float s = 0.f;
        #pragma unroll 8
        for (int c = 0; c < MT; c++) s += e_s[c] * __half2float(outh[c * OHP + tid]);
        g_blk_wout[(size_t)blk * 64 + tid] = s;
    } else if (tid == 64) {
        float s = 0.f;
        for (int c = 0; c < MT; c++) s += t_s[c];
        g_blk_t[blk] = s;
    } else if (tid == 96) {
        float s = 0.f;
        for (int c = 0; c < MT; c++) s += e_s[c];
        g_blk_e[blk] = s;
    }
}

// ---------------- kC: parallel partials + last-block combine (25 blocks) ----------------
__global__ __launch_bounds__(128) void kC(
    const float* __restrict__ Wo, const float* __restrict__ bo,
    float* __restrict__ dout)
{
    const int b = blockIdx.x;
    const int tid = threadIdx.x;
    __shared__ float s_comb[64];
    __shared__ float s_w[4], s_t[4];
    __shared__ int s_last;

    if (b < 8) {
        // faction sums: faction b, hidden j=tid; 256 kB-blocks per faction
        const float* p = g_blk_h + (size_t)(b * 256) * 128 + tid;
        float s = 0.f;
        #pragma unroll 8
        for (int k = 0; k < 256; k++) s += p[k * 128];
        g_fs[b * 128 + tid] = s;
        g_fm[b * 128 + tid] = s * (1.f / 16384.f);
    } else if (b < 24) {
        if (tid < 64) {
            // wout chunk (b-8): 128 kB-blocks x 64 outputs
            int ch = b - 8;
            const float* p = g_blk_wout + (size_t)(ch * 128) * 64 + tid;
            float s = 0.f;
            #pragma unroll 8
            for (int k = 0; k < 128; k++) s += p[k * 64];
            g_woutp[ch * 64 + tid] = s;
        }
    } else {
        // e/t sums over NBLK=2048
        float se = 0.f, st = 0.f;
        #pragma unroll 4
        for (int i = tid; i < NBLK; i += 128) { se += g_blk_e[i]; st += g_blk_t[i]; }
        #pragma unroll
        for (int off = 16; off > 0; off >>= 1) {
            se += __shfl_xor_sync(0xffffffffu, se, off);
            st += __shfl_xor_sync(0xffffffffu, st, off);
        }
        if ((tid & 31) == 0) { s_w[tid >> 5] = se; s_t[tid >> 5] = st; }
        __syncthreads();
        if (tid == 0) {
            float E = s_w[0] + s_w[1] + s_w[2] + s_w[3];
            float T = s_t[0] + s_t[1] + s_t[2] + s_t[3];
            g_esum_v = E;
            dout[64] = T * (1.f / (float)NCELLS);
        }
    }

    // ---- completion ticket; last block combines ----
    __syncthreads();
    __threadfence();
    if (tid == 0) s_last = (atomicAdd(&g_ctr, 1) == 24);
    __syncthreads();
    if (s_last) {
        // go = global mean from raw faction sums (fixed order)
        float gg = 0.f;
        #pragma unroll
        for (int f = 0; f < 8; f++) gg += g_fs[f * 128 + tid];
        g_go[tid] = gg * (1.f / (float)NCELLS);
        if (tid < 64) {
            float s = 0.f;
            #pragma unroll
            for (int ch = 0; ch < 16; ch++) s += g_woutp[ch * 64 + tid];
            s_comb[tid] = s * (1.f / g_esum_v);
        }
        __syncthreads();
        if (tid < 64) {
            float p = bo[tid];
            const float* wr = Wo + tid * 64;
            #pragma unroll 8
            for (int o = 0; o < 64; o++) p += wr[o] * s_comb[o];
            dout[tid] = p;
        }
        if (tid == 0) g_ctr = 0;   // reset for next (graph-replayed) call
    }
}

// ---------------- Kernel D: faction sync, float4 RMW, grid 4096 (2 f4/thread) ----------------
// nh = dout+65; nh+3 is 16B-aligned. Chunks cover e in [3, 16777215); peel e=0,1,2 and e=16777215.
__global__ __launch_bounds__(512) void kD(float* __restrict__ nh, const void* __restrict__ stepPtr)
{
    int iv = *(const int*)stepPtr;
    int step = (iv >= 0 && iv < 1000000) ? iv : (int)(*(const float*)stepPtr);
    const bool debate = (step > 5);

    if (blockIdx.x == 0 && threadIdx.x < 4) {
        unsigned e = (threadIdx.x < 3) ? threadIdx.x : 16777215u;
        unsigned cell = e >> 7, j = e & 127u;
        unsigned f = cell >> 14, pos = cell & 16383u;
        float v = nh[e];
        v = 0.85f * v + 0.15f * g_fm[f * 128 + j];
        if (debate && pos < 4096u) v = 0.85f * v + 0.15f * g_go[j];
        nh[e] = v;
    }

    float4* nh4 = (float4*)(nh + 3);
    unsigned base = blockIdx.x * 512u + threadIdx.x;
    const unsigned stride = 4096u * 512u;
    #pragma unroll
    for (int r = 0; r < 2; r++) {
        unsigned q = base + (unsigned)r * stride;
        if (q < 4194303u) {
            float4 v = nh4[q];
            float va[4] = {v.x, v.y, v.z, v.w};
            unsigned e0 = 3u + 4u * q;
            #pragma unroll
            for (int i = 0; i < 4; i++) {
                unsigned e = e0 + (unsigned)i;
                unsigned cell = e >> 7, j = e & 127u;
                unsigned f = cell >> 14, pos = cell & 16383u;
                float val = va[i];
                val = 0.85f * val + 0.15f * g_fm[f * 128 + j];
                if (debate && pos < 4096u) val = 0.85f * val + 0.15f * g_go[j];
                va[i] = val;
            }
            nh4[q] = make_float4(va[0], va[1], va[2], va[3]);
        }
    }
}

// ---------------- launcher ----------------
extern "C" void kernel_launch(void* const* d_in, const int* in_sizes, int n_in,
                              void* d_out, int out_size)
{
    const float* x    = (const float*)d_in[0];
    const float* hid  = (const float*)d_in[1];
    const float* W1a  = (const float*)d_in[2];
    const float* b1a  = (const float*)d_in[3];
    const float* W2a  = (const float*)d_in[4];
    const float* b2a  = (const float*)d_in[5];
    const float* W1g  = (const float*)d_in[6];
    const float* b1g  = (const float*)d_in[7];
    const float* W2g  = (const float*)d_in[8];
    const float* b2g  = (const float*)d_in[9];
    const float* Wih  = (const float*)d_in[10];
    const float* Whh  = (const float*)d_in[11];
    const float* bih  = (const float*)d_in[12];
    const float* bhh  = (const float*)d_in[13];
    const float* Wo   = (const float*)d_in[14];
    const float* bo   = (const float*)d_in[15];
    const void*  step = (n_in > 16) ? (const void*)d_in[16] : (const void*)d_in[15];

    float* out = (float*)d_out;
    float* nh  = out + 65;

    cudaFuncSetAttribute(kB, cudaFuncAttributeMaxDynamicSharedMemorySize, SMEM_KB_BYTES);

    kA<<<63, 512>>>(x, W1a, b1a, W1g, b1g, b2a, b2g, W2a, W2g, Wih, Whh, bih, bhh);
    kB<<<NBLK, TPB, SMEM_KB_BYTES>>>(hid, out);
    kC<<<25, 128>>>(Wo, bo, out);
    kD<<<4096, 512>>>(nh, step);
}